// round 12
// baseline (speedup 1.0000x reference)
#include <cuda_runtime.h>
#include <cuda_fp16.h>
#include <math.h>
#include <cstdint>

static constexpr int E_  = 8;
static constexpr int B_  = 8;
static constexpr int S_  = 512;
static constexpr int D_  = 768;
static constexpr int H_  = 12;
static constexpr int DH_ = 64;
static constexpr int DFF_= 3072;
static constexpr float SCALE_ = 0.03608439182435161f;  // 768^-0.5

// ---------------- scratch (device globals; allocation-free rule) ----------------
__device__ __align__(16) __half g_Qh [E_*B_*H_*S_*DH_];
__device__ __align__(16) __half g_Kh [E_*B_*H_*S_*DH_];
__device__ __align__(16) __half g_Vh [E_*B_*H_*S_*DH_];
__device__ __align__(16) __half g_ctx_h[(size_t)E_*B_*S_*D_];
__device__ __align__(16) float  g_cmp [E_*B_*8*D_];
__device__ __align__(16) float  g_feat[E_*B_*D_];
__device__ int    g_sel [B_];
__device__ __align__(16) float  g_att_sel[B_*S_*D_];
__device__ __align__(16) float  g_h   [B_*S_*D_];
__device__ __align__(16) __half g_h_h [B_*S_*D_];
__device__ __align__(16) __half g_mid_h[B_*S_*DFF_];
__device__ __align__(16) float  g_pre2[B_*S_*D_];
// fp16 converted operands
__device__ __align__(16) __half g_Xh   [B_*S_*D_];
__device__ __align__(16) __half g_Wqkvh[E_*H_*3*DH_*D_];
__device__ __align__(16) __half g_Wdh  [E_*D_*D_];
__device__ __align__(16) __half g_W1h  [E_*DFF_*D_];
__device__ __align__(16) __half g_W2h  [E_*D_*DFF_];

// ---------------- PTX helpers (base sm_103-safe: mma.sync / ldmatrix / cp.async) --
__device__ __forceinline__ void cpasync16(uint32_t dst, const void* src) {
    asm volatile("cp.async.cg.shared.global [%0], [%1], 16;"
                 :: "r"(dst), "l"(src) : "memory");
}
#define CP_COMMIT() asm volatile("cp.async.commit_group;" ::: "memory")
#define CP_WAIT0()  asm volatile("cp.async.wait_group 0;"  ::: "memory")
#define CP_WAIT1()  asm volatile("cp.async.wait_group 1;"  ::: "memory")

__device__ __forceinline__ void ldm_x4(uint32_t& r0, uint32_t& r1,
                                       uint32_t& r2, uint32_t& r3, uint32_t addr) {
    asm volatile("ldmatrix.sync.aligned.m8n8.x4.shared.b16 {%0,%1,%2,%3}, [%4];"
                 : "=r"(r0), "=r"(r1), "=r"(r2), "=r"(r3) : "r"(addr));
}
__device__ __forceinline__ void ldm_x4_t(uint32_t& r0, uint32_t& r1,
                                         uint32_t& r2, uint32_t& r3, uint32_t addr) {
    asm volatile("ldmatrix.sync.aligned.m8n8.x4.trans.shared.b16 {%0,%1,%2,%3}, [%4];"
                 : "=r"(r0), "=r"(r1), "=r"(r2), "=r"(r3) : "r"(addr));
}
__device__ __forceinline__ void mma16816(float* c, const uint32_t* a, const uint32_t* b) {
    asm volatile(
        "mma.sync.aligned.m16n8k16.row.col.f32.f16.f16.f32 "
        "{%0,%1,%2,%3},{%4,%5,%6,%7},{%8,%9},{%0,%1,%2,%3};"
        : "+f"(c[0]), "+f"(c[1]), "+f"(c[2]), "+f"(c[3])
        : "r"(a[0]), "r"(a[1]), "r"(a[2]), "r"(a[3]), "r"(b[0]), "r"(b[1]));
}
__device__ __forceinline__ uint32_t f22u(float a, float b) {
    __half2 h = __floats2half2_rn(a, b);
    return *(uint32_t*)&h;
}

// ---------------- block reduction ----------------
__device__ __forceinline__ float blockSum256(float v) {
    __shared__ float sh[8];
    int lane = threadIdx.x & 31, w = threadIdx.x >> 5;
    #pragma unroll
    for (int o = 16; o; o >>= 1) v += __shfl_xor_sync(0xffffffffu, v, o);
    if (lane == 0) sh[w] = v;
    __syncthreads();
    if (w == 0) {
        float t = (lane < 8) ? sh[lane] : 0.f;
        #pragma unroll
        for (int o = 4; o; o >>= 1) t += __shfl_xor_sync(0xffffffffu, t, o);
        if (lane == 0) sh[0] = t;
    }
    __syncthreads();
    float r = sh[0];
    __syncthreads();
    return r;
}

// ---------------- fp32 -> fp16 converters ----------------
template<int T>
__global__ void cvt_k(const float* __restrict__ src, int n) {
    __half* dst = (T == 0) ? g_Xh : g_Wqkvh;
    int i = (blockIdx.x * 256 + threadIdx.x) * 4;
    if (i >= n) return;
    float4 v = *(const float4*)&src[i];
    *(__half2*)&dst[i]     = __floats2half2_rn(v.x, v.y);
    *(__half2*)&dst[i + 2] = __floats2half2_rn(v.z, v.w);
}

// selection-gated converters (run after routing; skip unselected experts)
template<int T>
__global__ void cvt_sel_k(const float* __restrict__ src) {
    constexpr int PER = (T == 2) ? D_*D_ : DFF_*D_;
    __half* dst = (T == 2) ? g_Wdh : (T == 3) ? g_W1h : g_W2h;
    int i = (blockIdx.x * 256 + threadIdx.x) * 4;
    int e = i / PER;
    bool need = false;
    #pragma unroll
    for (int b = 0; b < B_; b++) need |= (g_sel[b] == e);
    if (!need) return;
    float4 v = *(const float4*)&src[i];
    *(__half2*)&dst[i]     = __floats2half2_rn(v.x, v.y);
    *(__half2*)&dst[i + 2] = __floats2half2_rn(v.z, v.w);
}

// ---------------- HMMA GEMM 128x128 (dense / ffn2) --------------------------------
static constexpr int TPAD  = 40;
static constexpr int TILEB = 128 * TPAD * 2;
static constexpr int BUFB  = 2 * TILEB;

template<int MODE>
__global__ void __launch_bounds__(256) hgemm_k(const float* __restrict__ bias,
                                               int K, int NIT)
{
    __shared__ __align__(128) __half smbuf[2 * 2 * 128 * TPAD];
    const uint32_t smb = (uint32_t)__cvta_generic_to_shared(smbuf);

    const int tid = threadIdx.x, lane = tid & 31, wid = tid >> 5;
    const int wm = (wid & 1) * 64, wn = (wid >> 1) * 32;
    const int z = blockIdx.z;
    const int bm = blockIdx.x * 128, bn = blockIdx.y * 128;

    const __half* A; const __half* W; const float* bvec;
    if (MODE == 1) {
        int e = g_sel[z];
        A = g_ctx_h + ((size_t)(e * B_ + z)) * S_ * D_;
        W = g_Wdh + (size_t)e * D_ * D_;   bvec = bias + e * D_;
    } else {
        int e = g_sel[z];
        A = g_mid_h + (size_t)z * S_ * DFF_;
        W = g_W2h + (size_t)e * D_ * DFF_; bvec = bias + e * D_;
    }

    auto load_tile = [&](int buf, int k0) {
        #pragma unroll
        for (int j = 0; j < 4; j++) {
            int i = tid + 256 * j;
            int row = (i & 511) >> 2, chunk = i & 3;
            const __half* src = (i < 512)
                ? &A[(size_t)(bm + row) * K + k0 + chunk * 8]
                : &W[(size_t)(bn + row) * K + k0 + chunk * 8];
            uint32_t dst = smb + buf * BUFB + ((i < 512) ? 0 : TILEB)
                         + (row * TPAD + chunk * 8) * 2;
            cpasync16(dst, src);
        }
        CP_COMMIT();
    };

    float acc[4][4][4];
    #pragma unroll
    for (int mi = 0; mi < 4; mi++)
        #pragma unroll
        for (int nj = 0; nj < 4; nj++)
            #pragma unroll
            for (int q = 0; q < 4; q++) acc[mi][nj][q] = 0.f;

    load_tile(0, 0);

    for (int it = 0; it < NIT; ++it) {
        CP_WAIT0();
        __syncthreads();
        if (it + 1 < NIT) load_tile((it + 1) & 1, (it + 1) * 32);

        const uint32_t base = smb + (it & 1) * BUFB;
        #pragma unroll
        for (int kst = 0; kst < 2; kst++) {
            uint32_t a[4][4];
            #pragma unroll
            for (int mi = 0; mi < 4; mi++) {
                int row = wm + mi * 16 + (lane & 15);
                uint32_t ad = base + (row * TPAD + kst * 16 + (lane >> 4) * 8) * 2;
                ldm_x4(a[mi][0], a[mi][1], a[mi][2], a[mi][3], ad);
            }
            uint32_t b[4][2];
            #pragma unroll
            for (int nh = 0; nh < 2; nh++) {
                int nrow = wn + nh * 16 + (lane & 7) + ((lane >> 4) & 1) * 8;
                int koff = ((lane >> 3) & 1) * 8;
                uint32_t bd = base + TILEB + (nrow * TPAD + kst * 16 + koff) * 2;
                ldm_x4(b[nh*2][0], b[nh*2][1], b[nh*2+1][0], b[nh*2+1][1], bd);
            }
            #pragma unroll
            for (int mi = 0; mi < 4; mi++)
                #pragma unroll
                for (int nj = 0; nj < 4; nj++)
                    mma16816(acc[mi][nj], a[mi], b[nj]);
        }
        __syncthreads();
    }

    #pragma unroll
    for (int mi = 0; mi < 4; mi++) {
        #pragma unroll
        for (int nj = 0; nj < 4; nj++) {
            int r0 = bm + wm + mi * 16 + (lane >> 2);
            int c0 = bn + wn + nj * 8 + (lane & 3) * 2;
            #pragma unroll
            for (int half_ = 0; half_ < 2; half_++) {
                int m = r0 + half_ * 8;
                float v0 = acc[mi][nj][half_ * 2 + 0];
                float v1 = acc[mi][nj][half_ * 2 + 1];
                int n = c0;
                if (MODE == 1) {
                    *(float2*)&g_att_sel[((size_t)z * S_ + m) * D_ + n] =
                        make_float2(v0 + bvec[n], v1 + bvec[n + 1]);
                } else {
                    size_t o = ((size_t)z * S_ + m) * D_ + n;
                    float2 hr = *(const float2*)&g_h[o];
                    *(float2*)&g_pre2[o] =
                        make_float2(v0 + bvec[n] + hr.x, v1 + bvec[n + 1] + hr.y);
                }
            }
        }
    }
}

// ---------------- HMMA GEMM 128x256 (QKV / ffn1): 8 warps, 64x64 warp tile --------
static constexpr int ATILE = 128 * TPAD * 2;   // 10240 B
static constexpr int BTILE = 256 * TPAD * 2;   // 20480 B
static constexpr int STAGE = ATILE + BTILE;    // 30720 B
static constexpr int GSM2  = 2 * STAGE;        // 61440 B

template<int MODE>
__global__ void __launch_bounds__(256) hgemm256_k(const float* __restrict__ bias,
                                                  int K, int NIT)
{
    extern __shared__ __align__(128) char smraw[];
    const uint32_t smb = (uint32_t)__cvta_generic_to_shared(smraw);

    const int tid = threadIdx.x, lane = tid & 31, wid = tid >> 5;
    const int wm = (wid & 1) * 64, wn = (wid >> 1) * 64;
    const int z = blockIdx.z;
    const int bm = blockIdx.x * 128, bn = blockIdx.y * 256;

    const __half* A; const __half* W; const float* bvec = nullptr;
    if (MODE == 0) {
        A = g_Xh; W = g_Wqkvh + (size_t)z * (H_*3*DH_) * D_;
    } else {
        int e = g_sel[z];
        A = g_h_h + (size_t)z * S_ * D_;
        W = g_W1h + (size_t)e * DFF_ * D_; bvec = bias + e * DFF_;
    }

    auto load_tile = [&](int buf, int k0) {
        #pragma unroll
        for (int j = 0; j < 6; j++) {
            int i = tid + 256 * j;
            uint32_t dst;
            const __half* src;
            if (i < 512) {
                int row = i >> 2, chunk = i & 3;
                src = &A[(size_t)(bm + row) * K + k0 + chunk * 8];
                dst = smb + buf * STAGE + (row * TPAD + chunk * 8) * 2;
            } else {
                int i2 = i - 512;
                int row = i2 >> 2, chunk = i2 & 3;
                src = &W[(size_t)(bn + row) * K + k0 + chunk * 8];
                dst = smb + buf * STAGE + ATILE + (row * TPAD + chunk * 8) * 2;
            }
            cpasync16(dst, src);
        }
        CP_COMMIT();
    };

    float acc[4][8][4];
    #pragma unroll
    for (int mi = 0; mi < 4; mi++)
        #pragma unroll
        for (int nj = 0; nj < 8; nj++)
            #pragma unroll
            for (int q = 0; q < 4; q++) acc[mi][nj][q] = 0.f;

    load_tile(0, 0);

    for (int it = 0; it < NIT; ++it) {
        CP_WAIT0();
        __syncthreads();
        if (it + 1 < NIT) load_tile((it + 1) & 1, (it + 1) * 32);

        const uint32_t base = smb + (it & 1) * STAGE;
        #pragma unroll
        for (int kst = 0; kst < 2; kst++) {
            uint32_t a[4][4];
            #pragma unroll
            for (int mi = 0; mi < 4; mi++) {
                int row = wm + mi * 16 + (lane & 15);
                uint32_t ad = base + (row * TPAD + kst * 16 + (lane >> 4) * 8) * 2;
                ldm_x4(a[mi][0], a[mi][1], a[mi][2], a[mi][3], ad);
            }
            uint32_t b[8][2];
            #pragma unroll
            for (int nb = 0; nb < 4; nb++) {
                int nrow = wn + nb * 16 + (lane & 7) + ((lane >> 4) & 1) * 8;
                int koff = ((lane >> 3) & 1) * 8;
                uint32_t bd = base + ATILE + (nrow * TPAD + kst * 16 + koff) * 2;
                ldm_x4(b[nb*2][0], b[nb*2][1], b[nb*2+1][0], b[nb*2+1][1], bd);
            }
            #pragma unroll
            for (int mi = 0; mi < 4; mi++)
                #pragma unroll
                for (int nj = 0; nj < 8; nj++)
                    mma16816(acc[mi][nj], a[mi], b[nj]);
        }
        __syncthreads();
    }

    #pragma unroll
    for (int mi = 0; mi < 4; mi++) {
        #pragma unroll
        for (int nj = 0; nj < 8; nj++) {
            int r0 = bm + wm + mi * 16 + (lane >> 2);
            int c0 = bn + wn + nj * 8 + (lane & 3) * 2;
            #pragma unroll
            for (int half_ = 0; half_ < 2; half_++) {
                int m = r0 + half_ * 8;
                float v0 = acc[mi][nj][half_ * 2 + 0];
                float v1 = acc[mi][nj][half_ * 2 + 1];
                int n = c0;
                if (MODE == 0) {
                    int hh = n / 192, rr = n % 192, w4 = rr >> 6, d = rr & 63;
                    int b8 = m >> 9, s = m & 511;
                    size_t idx = ((((size_t)z * B_ + b8) * H_ + hh) * S_ + s) * DH_ + d;
                    __half2 hv = __floats2half2_rn(v0, v1);
                    if      (w4 == 0) *(__half2*)&g_Qh[idx] = hv;
                    else if (w4 == 1) *(__half2*)&g_Kh[idx] = hv;
                    else              *(__half2*)&g_Vh[idx] = hv;
                } else {
                    float x0 = v0 + bvec[n], x1 = v1 + bvec[n + 1];
                    x0 = 0.5f * x0 * (1.f + erff(x0 * 0.70710678118654752f));
                    x1 = 0.5f * x1 * (1.f + erff(x1 * 0.70710678118654752f));
                    *(__half2*)&g_mid_h[((size_t)z * S_ + m) * DFF_ + n] =
                        __floats2half2_rn(x0, x1);
                }
            }
        }
    }
}

// ---------------- HMMA flash attention ------------------------------------------
static constexpr int FA_SMEM = 55808;

__global__ void __launch_bounds__(256) fattn_k(const int* __restrict__ mask)
{
    extern __shared__ __align__(128) char smem[];
    const uint32_t smb = (uint32_t)__cvta_generic_to_shared(smem);
    const uint32_t smQ = smb;
    const uint32_t smK = smb + 18432;
    const uint32_t smV = smb + 36864;
    float* mk = (float*)(smem + 55296);

    const int tid = threadIdx.x, lane = tid & 31, w = tid >> 5;
    const int i0 = blockIdx.x * 128, h = blockIdx.y, eb = blockIdx.z;
    const int b = eb & 7;
    const size_t hb = ((size_t)eb * H_ + h) * S_ * DH_;
    const __half* Qg = g_Qh + hb;
    const __half* Kg = g_Kh + hb;
    const __half* Vg = g_Vh + hb;

    #pragma unroll
    for (int j = 0; j < 4; j++) {
        int q = tid + 256 * j;
        int r = q >> 3, c = q & 7;
        cpasync16(smQ + r * 144 + c * 16, Qg + (size_t)(i0 + r) * 64 + c * 8);
    }
    #pragma unroll
    for (int j = 0; j < 4; j++) {
        int q = tid + 256 * j;
        int jr = (q & 511) >> 3, c = q & 7;
        const __half* src = (q < 512) ? (Kg + (size_t)jr * 64 + c * 8)
                                      : (Vg + (size_t)jr * 64 + c * 8);
        cpasync16(((q < 512) ? smK : smV) + jr * 144 + c * 16, src);
    }
    CP_COMMIT();
    if (tid < 64) mk[tid] = mask[b * S_ + tid] ? 0.f : -1e30f;

    float o[8][4];
    #pragma unroll
    for (int nd = 0; nd < 8; nd++)
        #pragma unroll
        for (int q = 0; q < 4; q++) o[nd][q] = 0.f;
    float m_run[2] = {-3.0e38f, -3.0e38f}, l_run[2] = {0.f, 0.f};
    uint32_t qa[4][4];

    const int kr = (lane & 7) + ((lane >> 4) & 1) * 8;
    const int kc = ((lane >> 3) & 1) * 8;
    const int vr = (lane & 7) + ((lane >> 3) & 1) * 8;
    const int vc = ((lane >> 4) & 1) * 8;
    const int cbase = 2 * (lane & 3);

    for (int jt = 0; jt < 8; jt++) {
        const int buf = jt & 1;
        if (jt < 7) {
            const int nb = buf ^ 1;
            const int j0n = (jt + 1) * 64;
            #pragma unroll
            for (int j = 0; j < 4; j++) {
                int q = tid + 256 * j;
                int jr = (q & 511) >> 3, c = q & 7;
                const __half* src = (q < 512) ? (Kg + (size_t)(j0n + jr) * 64 + c * 8)
                                              : (Vg + (size_t)(j0n + jr) * 64 + c * 8);
                cpasync16(((q < 512) ? smK : smV) + nb * 9216 + jr * 144 + c * 16, src);
            }
            CP_COMMIT();
            if (tid < 64) mk[nb * 64 + tid] = mask[b * S_ + j0n + tid] ? 0.f : -1e30f;
            CP_WAIT1();
        } else {
            CP_WAIT0();
        }
        __syncthreads();

        if (jt == 0) {
            #pragma unroll
            for (int kst = 0; kst < 4; kst++) {
                uint32_t ad = smQ + (w * 16 + (lane & 15)) * 144
                            + (kst * 16 + (lane >> 4) * 8) * 2;
                ldm_x4(qa[kst][0], qa[kst][1], qa[kst][2], qa[kst][3], ad);
            }
        }

        float sc[8][4];
        #pragma unroll
        for (int jb = 0; jb < 8; jb++)
            #pragma unroll
            for (int q = 0; q < 4; q++) sc[jb][q] = 0.f;
        const uint32_t kbase = smK + buf * 9216;
        #pragma unroll
        for (int kst = 0; kst < 4; kst++) {
            #pragma unroll
            for (int jb2 = 0; jb2 < 4; jb2++) {
                uint32_t addr = kbase + (jb2 * 16 + kr) * 144 + (kst * 16 + kc) * 2;
                uint32_t r4[4];
                ldm_x4(r4[0], r4[1], r4[2], r4[3], addr);
                mma16816(sc[2*jb2],     qa[kst], &r4[0]);
                mma16816(sc[2*jb2 + 1], qa[kst], &r4[2]);
            }
        }

        const float* mkb = mk + buf * 64;
        float mxA = -3.0e38f, mxB = -3.0e38f;
        #pragma unroll
        for (int jb = 0; jb < 8; jb++) {
            float m0 = mkb[jb * 8 + cbase], m1 = mkb[jb * 8 + cbase + 1];
            sc[jb][0] = sc[jb][0] * SCALE_ + m0;
            sc[jb][1] = sc[jb][1] * SCALE_ + m1;
            sc[jb][2] = sc[jb][2] * SCALE_ + m0;
            sc[jb][3] = sc[jb][3] * SCALE_ + m1;
            mxA = fmaxf(mxA, fmaxf(sc[jb][0], sc[jb][1]));
            mxB = fmaxf(mxB, fmaxf(sc[jb][2], sc[jb][3]));
        }
        mxA = fmaxf(mxA, __shfl_xor_sync(0xffffffffu, mxA, 1));
        mxA = fmaxf(mxA, __shfl_xor_sync(0xffffffffu, mxA, 2));
        mxB = fmaxf(mxB, __shfl_xor_sync(0xffffffffu, mxB, 1));
        mxB = fmaxf(mxB, __shfl_xor_sync(0xffffffffu, mxB, 2));
        float mA = fmaxf(m_run[0], mxA), mB = fmaxf(m_run[1], mxB);
        float cA = __expf(m_run[0] - mA), cB = __expf(m_run[1] - mB);
        float sA = 0.f, sB = 0.f;
        #pragma unroll
        for (int jb = 0; jb < 8; jb++) {
            sc[jb][0] = __expf(sc[jb][0] - mA); sA += sc[jb][0];
            sc[jb][1] = __expf(sc[jb][1] - mA); sA += sc[jb][1];
            sc[jb][2] = __expf(sc[jb][2] - mB); sB += sc[jb][2];
            sc[jb][3] = __expf(sc[jb][3] - mB); sB += sc[jb][3];
        }
        sA += __shfl_xor_sync(0xffffffffu, sA, 1);
        sA += __shfl_xor_sync(0xffffffffu, sA, 2);
        sB += __shfl_xor_sync(0xffffffffu, sB, 1);
        sB += __shfl_xor_sync(0xffffffffu, sB, 2);
        l_run[0] = l_run[0] * cA + sA; m_run[0] = mA;
        l_run[1] = l_run[1] * cB + sB; m_run[1] = mB;
        #pragma unroll
        for (int nd = 0; nd < 8; nd++) {
            o[nd][0] *= cA; o[nd][1] *= cA;
            o[nd][2] *= cB; o[nd][3] *= cB;
        }

        const uint32_t vbase = smV + buf * 9216;
        #pragma unroll
        for (int kst = 0; kst < 4; kst++) {
            uint32_t pa[4];
            pa[0] = f22u(sc[2*kst][0],     sc[2*kst][1]);
            pa[1] = f22u(sc[2*kst][2],     sc[2*kst][3]);
            pa[2] = f22u(sc[2*kst + 1][0], sc[2*kst + 1][1]);
            pa[3] = f22u(sc[2*kst + 1][2], sc[2*kst + 1][3]);
            #pragma unroll
            for (int nd2 = 0; nd2 < 4; nd2++) {
                uint32_t addr = vbase + (kst * 16 + vr) * 144 + (nd2 * 16 + vc) * 2;
                uint32_t r4[4];
                ldm_x4_t(r4[0], r4[1], r4[2], r4[3], addr);
                mma16816(o[2*nd2],     pa, &r4[0]);
                mma16816(o[2*nd2 + 1], pa, &r4[2]);
            }
        }
        __syncthreads();
    }

    float iA = 1.f / l_run[0], iB = 1.f / l_run[1];
    int rA = i0 + w * 16 + (lane >> 2);
    int rB = rA + 8;
    #pragma unroll
    for (int nd = 0; nd < 8; nd++) {
        int d0 = h * 64 + nd * 8 + cbase;
        *(__half2*)&g_ctx_h[((size_t)eb * S_ + rA) * D_ + d0] =
            __floats2half2_rn(o[nd][0] * iA, o[nd][1] * iA);
        *(__half2*)&g_ctx_h[((size_t)eb * S_ + rB) * D_ + d0] =
            __floats2half2_rn(o[nd][2] * iB, o[nd][3] * iB);
    }
}

// ---------------- partial seq-mean of ctx ----------------------------------------
__global__ void cmean_k()
{
    int eb = blockIdx.x, ch = blockIdx.y, t = threadIdx.x;
    const __half* base = g_ctx_h + ((size_t)eb * S_ + ch * 64) * D_;
    for (int c2 = t; c2 < 384; c2 += 256) {
        float sx = 0.f, sy = 0.f;
        for (int i = 0; i < 64; i++) {
            float2 f = __half22float2(*(const __half2*)&base[(size_t)i * D_ + 2*c2]);
            sx += f.x; sy += f.y;
        }
        *(float2*)&g_cmp[((size_t)eb * 8 + ch) * D_ + 2*c2] = make_float2(sx, sy);
    }
}

// ---------------- routing micro-GEMM: feat = mean(ctx)@Wd^T + bd -----------------
__global__ void featgemm_k(const float* __restrict__ Wd, const float* __restrict__ bd)
{
    __shared__ float cm[D_];
    int eb = blockIdx.x, t = threadIdx.x, e = eb >> 3;
    for (int c = t; c < D_; c += 256) {
        float s = 0.f;
        #pragma unroll
        for (int ch = 0; ch < 8; ch++) s += g_cmp[((size_t)eb * 8 + ch) * D_ + c];
        cm[c] = s * (1.f / 512.f);
    }
    __syncthreads();
    const float* We = Wd + (size_t)e * D_ * D_;
    for (int n = t; n < D_; n += 256) {
        float s = bd[e * D_ + n];
        const float4* wr = (const float4*)&We[(size_t)n * D_];
        for (int d4 = 0; d4 < D_/4; d4++) {
            float4 w = wr[d4];
            s += cm[d4*4]*w.x + cm[d4*4+1]*w.y + cm[d4*4+2]*w.z + cm[d4*4+3]*w.w;
        }
        g_feat[(size_t)eb * D_ + n] = s;
    }
}

// ---------------- route: sel[b] = argmin_e ||feat[e,b]-centers[e]|| ---------------
__global__ void route_k(const float* __restrict__ centers)
{
    int b = blockIdx.x, t = threadIdx.x;
    float bv = 3.4e38f; int bi = 0;
    for (int e = 0; e < E_; e++) {
        float ps = 0.f;
        for (int c = t; c < D_; c += 256) {
            float d0 = g_feat[(e*B_ + b)*D_ + c] - centers[e*D_ + c];
            ps += d0 * d0;
        }
        float tot = blockSum256(ps);
        if (t == 0 && tot < bv) { bv = tot; bi = e; }
    }
    if (t == 0) g_sel[b] = bi;
}

// ---------------- LN1: h = LN(att_sel + x) ----------------
__global__ void ln1_k(const float* __restrict__ X,
                      const float* __restrict__ gma, const float* __restrict__ bta)
{
    int s = blockIdx.x, b = blockIdx.y, t = threadIdx.x;
    int e = g_sel[b];
    const float* ar = g_att_sel + ((size_t)b*S_ + s) * D_;
    const float* xr = X + ((size_t)b*S_ + s) * D_;
    float v[3], sm = 0.f;
    #pragma unroll
    for (int i = 0; i < 3; i++) { int c = t + i*256; v[i] = ar[c] + xr[c]; sm += v[i]; }
    float mean = blockSum256(sm) * (1.f / D_);
    float q = 0.f;
    #pragma unroll
    for (int i = 0; i < 3; i++) { float d0 = v[i] - mean; q += d0 * d0; }
    float inv = rsqrtf(blockSum256(q) * (1.f / D_) + 1e-12f);
    float*  hr  = g_h   + ((size_t)b*S_ + s) * D_;
    __half* hrh = g_h_h + ((size_t)b*S_ + s) * D_;
    #pragma unroll
    for (int i = 0; i < 3; i++) {
        int c = t + i*256;
        float val = (v[i] - mean) * inv * gma[e*D_ + c] + bta[e*D_ + c];
        hr[c]  = val;
        hrh[c] = __float2half_rn(val);
    }
}

// ---------------- LN2: out = LN(pre2) ----------------
__global__ void ln2_k(float* __restrict__ out,
                      const float* __restrict__ gma, const float* __restrict__ bta)
{
    int s = blockIdx.x, b = blockIdx.y, t = threadIdx.x;
    int e = g_sel[b];
    const float* pr = g_pre2 + ((size_t)b*S_ + s) * D_;
    float v[3], sm = 0.f;
    #pragma unroll
    for (int i = 0; i < 3; i++) { int c = t + i*256; v[i] = pr[c]; sm += v[i]; }
    float mean = blockSum256(sm) * (1.f / D_);
    float q = 0.f;
    #pragma unroll
    for (int i = 0; i < 3; i++) { float d0 = v[i] - mean; q += d0 * d0; }
    float inv = rsqrtf(blockSum256(q) * (1.f / D_) + 1e-12f);
    float* orow = out + ((size_t)b*S_ + s) * D_;
    #pragma unroll
    for (int i = 0; i < 3; i++) {
        int c = t + i*256;
        orow[c] = (v[i] - mean) * inv * gma[e*D_ + c] + bta[e*D_ + c];
    }
}

// ---------------- launch ----------------
extern "C" void kernel_launch(void* const* d_in, const int* in_sizes, int n_in,
                              void* d_out, int out_size)
{
    const float* X      = (const float*)d_in[0];
    const int*   mask   = (const int*)  d_in[1];
    const float* Wqkv   = (const float*)d_in[2];
    const float* Wd     = (const float*)d_in[3];
    const float* bd     = (const float*)d_in[4];
    const float* ln1g   = (const float*)d_in[5];
    const float* ln1b   = (const float*)d_in[6];
    const float* W1     = (const float*)d_in[7];
    const float* b1     = (const float*)d_in[8];
    const float* W2     = (const float*)d_in[9];
    const float* b2     = (const float*)d_in[10];
    const float* ln2g   = (const float*)d_in[11];
    const float* ln2b   = (const float*)d_in[12];
    const float* centers= (const float*)d_in[13];
    float* out = (float*)d_out;

    cudaFuncSetAttribute(fattn_k, cudaFuncAttributeMaxDynamicSharedMemorySize, FA_SMEM);
    cudaFuncSetAttribute(hgemm256_k<0>, cudaFuncAttributeMaxDynamicSharedMemorySize, GSM2);
    cudaFuncSetAttribute(hgemm256_k<2>, cudaFuncAttributeMaxDynamicSharedMemorySize, GSM2);

    const int nX    = B_*S_*D_;
    const int nWqkv = E_*H_*3*DH_*D_;
    const int nWd   = E_*D_*D_;
    const int nW1   = E_*DFF_*D_;
    const int nW2   = E_*D_*DFF_;

    // 0) convert X and Wqkv only (rest gated on routing)
    cvt_k<0><<<nX/1024,    256>>>(X,    nX);
    cvt_k<1><<<nWqkv/1024, 256>>>(Wqkv, nWqkv);

    // 1) QKV for all experts: M=4096, N=2304, K=768, z=e (128x256 tiles)
    hgemm256_k<0><<<dim3(32, 9, 8), 256, GSM2>>>(nullptr, D_, 24);
    // 2) HMMA flash attention (all e,b) -> ctx fp16
    fattn_k<<<dim3(4, 12, 64), 256, FA_SMEM>>>(mask);
    // 3) routing: mean(ctx) -> micro dense (fp32 Wd) -> argmin
    cmean_k<<<dim3(64, 8), 256>>>();
    featgemm_k<<<64, 256>>>(Wd, bd);
    route_k<<<B_, 256>>>(centers);
    // 3b) convert only selected experts' weights
    cvt_sel_k<2><<<nWd/1024, 256>>>(Wd);
    cvt_sel_k<3><<<nW1/1024, 256>>>(W1);
    cvt_sel_k<4><<<nW2/1024, 256>>>(W2);
    // 4) dense projection ONLY for selected expert: M=512, N=768, K=768, z=b
    hgemm_k<1><<<dim3(4, 6, 8), 256>>>(bd, D_, 24);
    // 5) LN1
    ln1_k<<<dim3(S_, B_), 256>>>(X, ln1g, ln1b);
    // 6) FFN1 + GELU: M=512, N=3072, K=768, z=b (128x256 tiles)
    hgemm256_k<2><<<dim3(4, 12, 8), 256, GSM2>>>(b1, D_, 24);
    // 7) FFN2 + bias + residual: M=512, N=768, K=3072, z=b
    hgemm_k<3><<<dim3(4, 6, 8), 256>>>(b2, DFF_, 96);
    // 8) LN2 -> output
    ln2_k<<<dim3(S_, B_), 256>>>(out, ln2g, ln2b);
}

// round 13
// speedup vs baseline: 1.0422x; 1.0422x over previous
#include <cuda_runtime.h>
#include <cuda_fp16.h>
#include <math.h>
#include <cstdint>

static constexpr int E_  = 8;
static constexpr int B_  = 8;
static constexpr int S_  = 512;
static constexpr int D_  = 768;
static constexpr int H_  = 12;
static constexpr int DH_ = 64;
static constexpr int DFF_= 3072;
static constexpr float SCALE_ = 0.03608439182435161f;  // 768^-0.5
static constexpr float QSC_   = 0.05205923094702504f;  // SCALE_ * log2(e)

// ---------------- scratch (device globals; allocation-free rule) ----------------
__device__ __align__(16) __half g_Qh [E_*B_*H_*S_*DH_];
__device__ __align__(16) __half g_Kh [E_*B_*H_*S_*DH_];
__device__ __align__(16) __half g_Vh [E_*B_*H_*S_*DH_];
__device__ __align__(16) __half g_ctx_h[(size_t)E_*B_*S_*D_];
__device__ __align__(16) float  g_cmp [E_*B_*8*D_];
__device__ __align__(16) float  g_feat[E_*B_*D_];
__device__ int    g_sel [B_];
__device__ __align__(16) float  g_att_sel[B_*S_*D_];
__device__ __align__(16) float  g_h   [B_*S_*D_];
__device__ __align__(16) __half g_h_h [B_*S_*D_];
__device__ __align__(16) __half g_mid_h[B_*S_*DFF_];
__device__ __align__(16) float  g_pre2[B_*S_*D_];
// fp16 converted operands
__device__ __align__(16) __half g_Xh   [B_*S_*D_];
__device__ __align__(16) __half g_Wqkvh[E_*H_*3*DH_*D_];
__device__ __align__(16) __half g_Wdh  [E_*D_*D_];
__device__ __align__(16) __half g_W1h  [E_*DFF_*D_];
__device__ __align__(16) __half g_W2h  [E_*D_*DFF_];

// ---------------- PTX helpers ----------------
__device__ __forceinline__ void cpasync16(uint32_t dst, const void* src) {
    asm volatile("cp.async.cg.shared.global [%0], [%1], 16;"
                 :: "r"(dst), "l"(src) : "memory");
}
#define CP_COMMIT() asm volatile("cp.async.commit_group;" ::: "memory")
#define CP_WAIT0()  asm volatile("cp.async.wait_group 0;"  ::: "memory")
#define CP_WAIT1()  asm volatile("cp.async.wait_group 1;"  ::: "memory")

__device__ __forceinline__ void ldm_x4(uint32_t& r0, uint32_t& r1,
                                       uint32_t& r2, uint32_t& r3, uint32_t addr) {
    asm volatile("ldmatrix.sync.aligned.m8n8.x4.shared.b16 {%0,%1,%2,%3}, [%4];"
                 : "=r"(r0), "=r"(r1), "=r"(r2), "=r"(r3) : "r"(addr));
}
__device__ __forceinline__ void ldm_x4_t(uint32_t& r0, uint32_t& r1,
                                         uint32_t& r2, uint32_t& r3, uint32_t addr) {
    asm volatile("ldmatrix.sync.aligned.m8n8.x4.trans.shared.b16 {%0,%1,%2,%3}, [%4];"
                 : "=r"(r0), "=r"(r1), "=r"(r2), "=r"(r3) : "r"(addr));
}
__device__ __forceinline__ void mma16816(float* c, const uint32_t* a, const uint32_t* b) {
    asm volatile(
        "mma.sync.aligned.m16n8k16.row.col.f32.f16.f16.f32 "
        "{%0,%1,%2,%3},{%4,%5,%6,%7},{%8,%9},{%0,%1,%2,%3};"
        : "+f"(c[0]), "+f"(c[1]), "+f"(c[2]), "+f"(c[3])
        : "r"(a[0]), "r"(a[1]), "r"(a[2]), "r"(a[3]), "r"(b[0]), "r"(b[1]));
}
__device__ __forceinline__ uint32_t f22u(float a, float b) {
    __half2 h = __floats2half2_rn(a, b);
    return *(uint32_t*)&h;
}

// ---------------- block reduction ----------------
__device__ __forceinline__ float blockSum256(float v) {
    __shared__ float sh[8];
    int lane = threadIdx.x & 31, w = threadIdx.x >> 5;
    #pragma unroll
    for (int o = 16; o; o >>= 1) v += __shfl_xor_sync(0xffffffffu, v, o);
    if (lane == 0) sh[w] = v;
    __syncthreads();
    if (w == 0) {
        float t = (lane < 8) ? sh[lane] : 0.f;
        #pragma unroll
        for (int o = 4; o; o >>= 1) t += __shfl_xor_sync(0xffffffffu, t, o);
        if (lane == 0) sh[0] = t;
    }
    __syncthreads();
    float r = sh[0];
    __syncthreads();
    return r;
}

// ---------------- fp32 -> fp16 converters ----------------
template<int T>
__global__ void cvt_k(const float* __restrict__ src, int n) {
    __half* dst = (T == 0) ? g_Xh : g_Wqkvh;
    int i = (blockIdx.x * 256 + threadIdx.x) * 4;
    if (i >= n) return;
    float4 v = *(const float4*)&src[i];
    *(__half2*)&dst[i]     = __floats2half2_rn(v.x, v.y);
    *(__half2*)&dst[i + 2] = __floats2half2_rn(v.z, v.w);
}

// selection-gated converters (run after routing; skip unselected experts)
template<int T>
__global__ void cvt_sel_k(const float* __restrict__ src) {
    constexpr int PER = (T == 2) ? D_*D_ : DFF_*D_;
    __half* dst = (T == 2) ? g_Wdh : (T == 3) ? g_W1h : g_W2h;
    int i = (blockIdx.x * 256 + threadIdx.x) * 4;
    int e = i / PER;
    bool need = false;
    #pragma unroll
    for (int b = 0; b < B_; b++) need |= (g_sel[b] == e);
    if (!need) return;
    float4 v = *(const float4*)&src[i];
    *(__half2*)&dst[i]     = __floats2half2_rn(v.x, v.y);
    *(__half2*)&dst[i + 2] = __floats2half2_rn(v.z, v.w);
}

// ---------------- HMMA GEMM 128x128, 3-stage cp.async pipeline -------------------
// MODE 0: QKV   z=e, A=Xh,           W=Wqkvh[e] -> scatter g_Q/K/V (fp16, Q pre-scaled)
// MODE 1: dense z=b, A=ctx_h[sel,b], W=Wdh[sel]+bd -> g_att_sel (fp32)
// MODE 2: ffn1  z=b, A=g_h_h[b],     W=W1h[sel]+b1, gelu -> g_mid_h
// MODE 3: ffn2  z=b, A=g_mid_h[b],   W=W2h[sel]+b2, +g_h -> g_pre2
static constexpr int TPAD  = 40;
static constexpr int TILEB = 128 * TPAD * 2;   // 10240 B
static constexpr int BUFB  = 2 * TILEB;        // 20480 B per stage
static constexpr int GSM3  = 3 * BUFB;         // 61440 B dynamic

template<int MODE>
__global__ void __launch_bounds__(256) hgemm_k(const float* __restrict__ bias,
                                               int K, int NIT)
{
    extern __shared__ __align__(128) char smraw[];
    const uint32_t smb = (uint32_t)__cvta_generic_to_shared(smraw);

    const int tid = threadIdx.x, lane = tid & 31, wid = tid >> 5;
    const int wm = (wid & 1) * 64, wn = (wid >> 1) * 32;
    const int z = blockIdx.z;
    const int bm = blockIdx.x * 128, bn = blockIdx.y * 128;

    const __half* A; const __half* W; const float* bvec = nullptr;
    if (MODE == 0) {
        A = g_Xh; W = g_Wqkvh + (size_t)z * (H_*3*DH_) * D_;
    } else if (MODE == 1) {
        int e = g_sel[z];
        A = g_ctx_h + ((size_t)(e * B_ + z)) * S_ * D_;
        W = g_Wdh + (size_t)e * D_ * D_;   bvec = bias + e * D_;
    } else if (MODE == 2) {
        int e = g_sel[z];
        A = g_h_h + (size_t)z * S_ * D_;
        W = g_W1h + (size_t)e * DFF_ * D_; bvec = bias + e * DFF_;
    } else {
        int e = g_sel[z];
        A = g_mid_h + (size_t)z * S_ * DFF_;
        W = g_W2h + (size_t)e * D_ * DFF_; bvec = bias + e * D_;
    }

    auto load_tile = [&](int buf, int k0) {
        #pragma unroll
        for (int j = 0; j < 4; j++) {
            int i = tid + 256 * j;
            int row = (i & 511) >> 2, chunk = i & 3;
            const __half* src = (i < 512)
                ? &A[(size_t)(bm + row) * K + k0 + chunk * 8]
                : &W[(size_t)(bn + row) * K + k0 + chunk * 8];
            uint32_t dst = smb + buf * BUFB + ((i < 512) ? 0 : TILEB)
                         + (row * TPAD + chunk * 8) * 2;
            cpasync16(dst, src);
        }
        CP_COMMIT();
    };

    float acc[4][4][4];
    #pragma unroll
    for (int mi = 0; mi < 4; mi++)
        #pragma unroll
        for (int nj = 0; nj < 4; nj++)
            #pragma unroll
            for (int q = 0; q < 4; q++) acc[mi][nj][q] = 0.f;

    load_tile(0, 0);
    load_tile(1, 32);

    for (int it = 0; it < NIT; ++it) {
        if (it >= NIT - 1) { CP_WAIT0(); } else { CP_WAIT1(); }
        __syncthreads();
        if (it + 2 < NIT) load_tile((it + 2) % 3, (it + 2) * 32);

        const uint32_t base = smb + (it % 3) * BUFB;
        #pragma unroll
        for (int kst = 0; kst < 2; kst++) {
            uint32_t a[4][4];
            #pragma unroll
            for (int mi = 0; mi < 4; mi++) {
                int row = wm + mi * 16 + (lane & 15);
                uint32_t ad = base + (row * TPAD + kst * 16 + (lane >> 4) * 8) * 2;
                ldm_x4(a[mi][0], a[mi][1], a[mi][2], a[mi][3], ad);
            }
            uint32_t b[4][2];
            #pragma unroll
            for (int nh = 0; nh < 2; nh++) {
                int nrow = wn + nh * 16 + (lane & 7) + ((lane >> 4) & 1) * 8;
                int koff = ((lane >> 3) & 1) * 8;
                uint32_t bd = base + TILEB + (nrow * TPAD + kst * 16 + koff) * 2;
                ldm_x4(b[nh*2][0], b[nh*2][1], b[nh*2+1][0], b[nh*2+1][1], bd);
            }
            #pragma unroll
            for (int mi = 0; mi < 4; mi++)
                #pragma unroll
                for (int nj = 0; nj < 4; nj++)
                    mma16816(acc[mi][nj], a[mi], b[nj]);
        }
        __syncthreads();
    }

    #pragma unroll
    for (int mi = 0; mi < 4; mi++) {
        #pragma unroll
        for (int nj = 0; nj < 4; nj++) {
            int r0 = bm + wm + mi * 16 + (lane >> 2);
            int c0 = bn + wn + nj * 8 + (lane & 3) * 2;
            #pragma unroll
            for (int half_ = 0; half_ < 2; half_++) {
                int m = r0 + half_ * 8;
                float v0 = acc[mi][nj][half_ * 2 + 0];
                float v1 = acc[mi][nj][half_ * 2 + 1];
                int n = c0;
                if (MODE == 0) {
                    int hh = n / 192, rr = n % 192, w4 = rr >> 6, d = rr & 63;
                    int b8 = m >> 9, s = m & 511;
                    size_t idx = ((((size_t)z * B_ + b8) * H_ + hh) * S_ + s) * DH_ + d;
                    if (w4 == 0)
                        *(__half2*)&g_Qh[idx] = __floats2half2_rn(v0 * QSC_, v1 * QSC_);
                    else if (w4 == 1)
                        *(__half2*)&g_Kh[idx] = __floats2half2_rn(v0, v1);
                    else
                        *(__half2*)&g_Vh[idx] = __floats2half2_rn(v0, v1);
                } else if (MODE == 1) {
                    *(float2*)&g_att_sel[((size_t)z * S_ + m) * D_ + n] =
                        make_float2(v0 + bvec[n], v1 + bvec[n + 1]);
                } else if (MODE == 2) {
                    float x0 = v0 + bvec[n], x1 = v1 + bvec[n + 1];
                    x0 = 0.5f * x0 * (1.f + erff(x0 * 0.70710678118654752f));
                    x1 = 0.5f * x1 * (1.f + erff(x1 * 0.70710678118654752f));
                    *(__half2*)&g_mid_h[((size_t)z * S_ + m) * DFF_ + n] =
                        __floats2half2_rn(x0, x1);
                } else {
                    size_t o = ((size_t)z * S_ + m) * D_ + n;
                    float2 hr = *(const float2*)&g_h[o];
                    *(float2*)&g_pre2[o] =
                        make_float2(v0 + bvec[n] + hr.x, v1 + bvec[n + 1] + hr.y);
                }
            }
        }
    }
}

// ---------------- HMMA flash attention (exp2-domain softmax) ---------------------
// Q pre-scaled by SCALE*log2(e) in the QKV epilogue.
static constexpr int FA_SMEM = 55808;

__global__ void __launch_bounds__(256) fattn_k(const int* __restrict__ mask)
{
    extern __shared__ __align__(128) char smem[];
    const uint32_t smb = (uint32_t)__cvta_generic_to_shared(smem);
    const uint32_t smQ = smb;
    const uint32_t smK = smb + 18432;
    const uint32_t smV = smb + 36864;
    float* mk = (float*)(smem + 55296);

    const int tid = threadIdx.x, lane = tid & 31, w = tid >> 5;
    const int i0 = blockIdx.x * 128, h = blockIdx.y, eb = blockIdx.z;
    const int b = eb & 7;
    const size_t hb = ((size_t)eb * H_ + h) * S_ * DH_;
    const __half* Qg = g_Qh + hb;
    const __half* Kg = g_Kh + hb;
    const __half* Vg = g_Vh + hb;

    #pragma unroll
    for (int j = 0; j < 4; j++) {
        int q = tid + 256 * j;
        int r = q >> 3, c = q & 7;
        cpasync16(smQ + r * 144 + c * 16, Qg + (size_t)(i0 + r) * 64 + c * 8);
    }
    #pragma unroll
    for (int j = 0; j < 4; j++) {
        int q = tid + 256 * j;
        int jr = (q & 511) >> 3, c = q & 7;
        const __half* src = (q < 512) ? (Kg + (size_t)jr * 64 + c * 8)
                                      : (Vg + (size_t)jr * 64 + c * 8);
        cpasync16(((q < 512) ? smK : smV) + jr * 144 + c * 16, src);
    }
    CP_COMMIT();
    if (tid < 64) mk[tid] = mask[b * S_ + tid] ? 0.f : -1e30f;

    float o[8][4];
    #pragma unroll
    for (int nd = 0; nd < 8; nd++)
        #pragma unroll
        for (int q = 0; q < 4; q++) o[nd][q] = 0.f;
    float m_run[2] = {-3.0e38f, -3.0e38f}, l_run[2] = {0.f, 0.f};
    uint32_t qa[4][4];

    const int kr = (lane & 7) + ((lane >> 4) & 1) * 8;
    const int kc = ((lane >> 3) & 1) * 8;
    const int vr = (lane & 7) + ((lane >> 3) & 1) * 8;
    const int vc = ((lane >> 4) & 1) * 8;
    const int cbase = 2 * (lane & 3);

    for (int jt = 0; jt < 8; jt++) {
        const int buf = jt & 1;
        if (jt < 7) {
            const int nb = buf ^ 1;
            const int j0n = (jt + 1) * 64;
            #pragma unroll
            for (int j = 0; j < 4; j++) {
                int q = tid + 256 * j;
                int jr = (q & 511) >> 3, c = q & 7;
                const __half* src = (q < 512) ? (Kg + (size_t)(j0n + jr) * 64 + c * 8)
                                              : (Vg + (size_t)(j0n + jr) * 64 + c * 8);
                cpasync16(((q < 512) ? smK : smV) + nb * 9216 + jr * 144 + c * 16, src);
            }
            CP_COMMIT();
            if (tid < 64) mk[nb * 64 + tid] = mask[b * S_ + j0n + tid] ? 0.f : -1e30f;
            CP_WAIT1();
        } else {
            CP_WAIT0();
        }
        __syncthreads();

        if (jt == 0) {
            #pragma unroll
            for (int kst = 0; kst < 4; kst++) {
                uint32_t ad = smQ + (w * 16 + (lane & 15)) * 144
                            + (kst * 16 + (lane >> 4) * 8) * 2;
                ldm_x4(qa[kst][0], qa[kst][1], qa[kst][2], qa[kst][3], ad);
            }
        }

        // S = Q K^T (already in log2 domain via pre-scaled Q)
        float sc[8][4];
        #pragma unroll
        for (int jb = 0; jb < 8; jb++)
            #pragma unroll
            for (int q = 0; q < 4; q++) sc[jb][q] = 0.f;
        const uint32_t kbase = smK + buf * 9216;
        #pragma unroll
        for (int kst = 0; kst < 4; kst++) {
            #pragma unroll
            for (int jb2 = 0; jb2 < 4; jb2++) {
                uint32_t addr = kbase + (jb2 * 16 + kr) * 144 + (kst * 16 + kc) * 2;
                uint32_t r4[4];
                ldm_x4(r4[0], r4[1], r4[2], r4[3], addr);
                mma16816(sc[2*jb2],     qa[kst], &r4[0]);
                mma16816(sc[2*jb2 + 1], qa[kst], &r4[2]);
            }
        }

        const float* mkb = mk + buf * 64;
        float mxA = -3.0e38f, mxB = -3.0e38f;
        #pragma unroll
        for (int jb = 0; jb < 8; jb++) {
            float m0 = mkb[jb * 8 + cbase], m1 = mkb[jb * 8 + cbase + 1];
            sc[jb][0] += m0;
            sc[jb][1] += m1;
            sc[jb][2] += m0;
            sc[jb][3] += m1;
            mxA = fmaxf(mxA, fmaxf(sc[jb][0], sc[jb][1]));
            mxB = fmaxf(mxB, fmaxf(sc[jb][2], sc[jb][3]));
        }
        mxA = fmaxf(mxA, __shfl_xor_sync(0xffffffffu, mxA, 1));
        mxA = fmaxf(mxA, __shfl_xor_sync(0xffffffffu, mxA, 2));
        mxB = fmaxf(mxB, __shfl_xor_sync(0xffffffffu, mxB, 1));
        mxB = fmaxf(mxB, __shfl_xor_sync(0xffffffffu, mxB, 2));
        float mA = fmaxf(m_run[0], mxA), mB = fmaxf(m_run[1], mxB);
        float cA = exp2f(m_run[0] - mA), cB = exp2f(m_run[1] - mB);
        float sA = 0.f, sB = 0.f;
        #pragma unroll
        for (int jb = 0; jb < 8; jb++) {
            sc[jb][0] = exp2f(sc[jb][0] - mA); sA += sc[jb][0];
            sc[jb][1] = exp2f(sc[jb][1] - mA); sA += sc[jb][1];
            sc[jb][2] = exp2f(sc[jb][2] - mB); sB += sc[jb][2];
            sc[jb][3] = exp2f(sc[jb][3] - mB); sB += sc[jb][3];
        }
        sA += __shfl_xor_sync(0xffffffffu, sA, 1);
        sA += __shfl_xor_sync(0xffffffffu, sA, 2);
        sB += __shfl_xor_sync(0xffffffffu, sB, 1);
        sB += __shfl_xor_sync(0xffffffffu, sB, 2);
        l_run[0] = l_run[0] * cA + sA; m_run[0] = mA;
        l_run[1] = l_run[1] * cB + sB; m_run[1] = mB;
        #pragma unroll
        for (int nd = 0; nd < 8; nd++) {
            o[nd][0] *= cA; o[nd][1] *= cA;
            o[nd][2] *= cB; o[nd][3] *= cB;
        }

        const uint32_t vbase = smV + buf * 9216;
        #pragma unroll
        for (int kst = 0; kst < 4; kst++) {
            uint32_t pa[4];
            pa[0] = f22u(sc[2*kst][0],     sc[2*kst][1]);
            pa[1] = f22u(sc[2*kst][2],     sc[2*kst][3]);
            pa[2] = f22u(sc[2*kst + 1][0], sc[2*kst + 1][1]);
            pa[3] = f22u(sc[2*kst + 1][2], sc[2*kst + 1][3]);
            #pragma unroll
            for (int nd2 = 0; nd2 < 4; nd2++) {
                uint32_t addr = vbase + (kst * 16 + vr) * 144 + (nd2 * 16 + vc) * 2;
                uint32_t r4[4];
                ldm_x4_t(r4[0], r4[1], r4[2], r4[3], addr);
                mma16816(o[2*nd2],     pa, &r4[0]);
                mma16816(o[2*nd2 + 1], pa, &r4[2]);
            }
        }
        __syncthreads();
    }

    float iA = 1.f / l_run[0], iB = 1.f / l_run[1];
    int rA = i0 + w * 16 + (lane >> 2);
    int rB = rA + 8;
    #pragma unroll
    for (int nd = 0; nd < 8; nd++) {
        int d0 = h * 64 + nd * 8 + cbase;
        *(__half2*)&g_ctx_h[((size_t)eb * S_ + rA) * D_ + d0] =
            __floats2half2_rn(o[nd][0] * iA, o[nd][1] * iA);
        *(__half2*)&g_ctx_h[((size_t)eb * S_ + rB) * D_ + d0] =
            __floats2half2_rn(o[nd][2] * iB, o[nd][3] * iB);
    }
}

// ---------------- partial seq-mean of ctx ----------------------------------------
__global__ void cmean_k()
{
    int eb = blockIdx.x, ch = blockIdx.y, t = threadIdx.x;
    const __half* base = g_ctx_h + ((size_t)eb * S_ + ch * 64) * D_;
    for (int c2 = t; c2 < 384; c2 += 256) {
        float sx = 0.f, sy = 0.f;
        for (int i = 0; i < 64; i++) {
            float2 f = __half22float2(*(const __half2*)&base[(size_t)i * D_ + 2*c2]);
            sx += f.x; sy += f.y;
        }
        *(float2*)&g_cmp[((size_t)eb * 8 + ch) * D_ + 2*c2] = make_float2(sx, sy);
    }
}

// ---------------- routing micro-GEMM: feat = mean(ctx)@Wd^T + bd -----------------
__global__ void featgemm_k(const float* __restrict__ Wd, const float* __restrict__ bd)
{
    __shared__ float cm[D_];
    int eb = blockIdx.x, t = threadIdx.x, e = eb >> 3;
    for (int c = t; c < D_; c += 256) {
        float s = 0.f;
        #pragma unroll
        for (int ch = 0; ch < 8; ch++) s += g_cmp[((size_t)eb * 8 + ch) * D_ + c];
        cm[c] = s * (1.f / 512.f);
    }
    __syncthreads();
    const float* We = Wd + (size_t)e * D_ * D_;
    for (int n = t; n < D_; n += 256) {
        float s = bd[e * D_ + n];
        const float4* wr = (const float4*)&We[(size_t)n * D_];
        for (int d4 = 0; d4 < D_/4; d4++) {
            float4 w = wr[d4];
            s += cm[d4*4]*w.x + cm[d4*4+1]*w.y + cm[d4*4+2]*w.z + cm[d4*4+3]*w.w;
        }
        g_feat[(size_t)eb * D_ + n] = s;
    }
}

// ---------------- route: sel[b] = argmin_e ||feat[e,b]-centers[e]|| ---------------
__global__ void route_k(const float* __restrict__ centers)
{
    int b = blockIdx.x, t = threadIdx.x;
    float bv = 3.4e38f; int bi = 0;
    for (int e = 0; e < E_; e++) {
        float ps = 0.f;
        for (int c = t; c < D_; c += 256) {
            float d0 = g_feat[(e*B_ + b)*D_ + c] - centers[e*D_ + c];
            ps += d0 * d0;
        }
        float tot = blockSum256(ps);
        if (t == 0 && tot < bv) { bv = tot; bi = e; }
    }
    if (t == 0) g_sel[b] = bi;
}

// ---------------- LN1: h = LN(att_sel + x) ----------------
__global__ void ln1_k(const float* __restrict__ X,
                      const float* __restrict__ gma, const float* __restrict__ bta)
{
    int s = blockIdx.x, b = blockIdx.y, t = threadIdx.x;
    int e = g_sel[b];
    const float* ar = g_att_sel + ((size_t)b*S_ + s) * D_;
    const float* xr = X + ((size_t)b*S_ + s) * D_;
    float v[3], sm = 0.f;
    #pragma unroll
    for (int i = 0; i < 3; i++) { int c = t + i*256; v[i] = ar[c] + xr[c]; sm += v[i]; }
    float mean = blockSum256(sm) * (1.f / D_);
    float q = 0.f;
    #pragma unroll
    for (int i = 0; i < 3; i++) { float d0 = v[i] - mean; q += d0 * d0; }
    float inv = rsqrtf(blockSum256(q) * (1.f / D_) + 1e-12f);
    float*  hr  = g_h   + ((size_t)b*S_ + s) * D_;
    __half* hrh = g_h_h + ((size_t)b*S_ + s) * D_;
    #pragma unroll
    for (int i = 0; i < 3; i++) {
        int c = t + i*256;
        float val = (v[i] - mean) * inv * gma[e*D_ + c] + bta[e*D_ + c];
        hr[c]  = val;
        hrh[c] = __float2half_rn(val);
    }
}

// ---------------- LN2: out = LN(pre2) ----------------
__global__ void ln2_k(float* __restrict__ out,
                      const float* __restrict__ gma, const float* __restrict__ bta)
{
    int s = blockIdx.x, b = blockIdx.y, t = threadIdx.x;
    int e = g_sel[b];
    const float* pr = g_pre2 + ((size_t)b*S_ + s) * D_;
    float v[3], sm = 0.f;
    #pragma unroll
    for (int i = 0; i < 3; i++) { int c = t + i*256; v[i] = pr[c]; sm += v[i]; }
    float mean = blockSum256(sm) * (1.f / D_);
    float q = 0.f;
    #pragma unroll
    for (int i = 0; i < 3; i++) { float d0 = v[i] - mean; q += d0 * d0; }
    float inv = rsqrtf(blockSum256(q) * (1.f / D_) + 1e-12f);
    float* orow = out + ((size_t)b*S_ + s) * D_;
    #pragma unroll
    for (int i = 0; i < 3; i++) {
        int c = t + i*256;
        orow[c] = (v[i] - mean) * inv * gma[e*D_ + c] + bta[e*D_ + c];
    }
}

// ---------------- launch ----------------
extern "C" void kernel_launch(void* const* d_in, const int* in_sizes, int n_in,
                              void* d_out, int out_size)
{
    const float* X      = (const float*)d_in[0];
    const int*   mask   = (const int*)  d_in[1];
    const float* Wqkv   = (const float*)d_in[2];
    const float* Wd     = (const float*)d_in[3];
    const float* bd     = (const float*)d_in[4];
    const float* ln1g   = (const float*)d_in[5];
    const float* ln1b   = (const float*)d_in[6];
    const float* W1     = (const float*)d_in[7];
    const float* b1     = (const float*)d_in[8];
    const float* W2     = (const float*)d_in[9];
    const float* b2     = (const float*)d_in[10];
    const float* ln2g   = (const float*)d_in[11];
    const float* ln2b   = (const float*)d_in[12];
    const float* centers= (const float*)d_in[13];
    float* out = (float*)d_out;

    cudaFuncSetAttribute(fattn_k, cudaFuncAttributeMaxDynamicSharedMemorySize, FA_SMEM);
    cudaFuncSetAttribute(hgemm_k<0>, cudaFuncAttributeMaxDynamicSharedMemorySize, GSM3);
    cudaFuncSetAttribute(hgemm_k<1>, cudaFuncAttributeMaxDynamicSharedMemorySize, GSM3);
    cudaFuncSetAttribute(hgemm_k<2>, cudaFuncAttributeMaxDynamicSharedMemorySize, GSM3);
    cudaFuncSetAttribute(hgemm_k<3>, cudaFuncAttributeMaxDynamicSharedMemorySize, GSM3);

    const int nX    = B_*S_*D_;
    const int nWqkv = E_*H_*3*DH_*D_;
    const int nWd   = E_*D_*D_;
    const int nW1   = E_*DFF_*D_;
    const int nW2   = E_*D_*DFF_;

    // 0) convert X and Wqkv (rest gated on routing)
    cvt_k<0><<<nX/1024,    256>>>(X,    nX);
    cvt_k<1><<<nWqkv/1024, 256>>>(Wqkv, nWqkv);

    // 1) QKV for all experts: M=4096, N=2304, K=768, z=e
    hgemm_k<0><<<dim3(32, 18, 8), 256, GSM3>>>(nullptr, D_, 24);
    // 2) HMMA flash attention (all e,b) -> ctx fp16
    fattn_k<<<dim3(4, 12, 64), 256, FA_SMEM>>>(mask);
    // 3) routing: mean(ctx) -> micro dense (fp32 Wd) -> argmin
    cmean_k<<<dim3(64, 8), 256>>>();
    featgemm_k<<<64, 256>>>(Wd, bd);
    route_k<<<B_, 256>>>(centers);
    // 3b) convert only selected experts' weights
    cvt_sel_k<2><<<nWd/1024, 256>>>(Wd);
    cvt_sel_k<3><<<nW1/1024, 256>>>(W1);
    cvt_sel_k<4><<<nW2/1024, 256>>>(W2);
    // 4) dense projection ONLY for selected expert: M=512, N=768, K=768, z=b
    hgemm_k<1><<<dim3(4, 6, 8), 256, GSM3>>>(bd, D_, 24);
    // 5) LN1
    ln1_k<<<dim3(S_, B_), 256>>>(X, ln1g, ln1b);
    // 6) FFN1 + GELU: M=512, N=3072, K=768, z=b
    hgemm_k<2><<<dim3(4, 24, 8), 256, GSM3>>>(b1, D_, 24);
    // 7) FFN2 + bias + residual: M=512, N=768, K=3072, z=b
    hgemm_k<3><<<dim3(4, 6, 8), 256, GSM3>>>(b2, DFF_, 96);
    // 8) LN2 -> output
    ln2_k<<<dim3(S_, B_), 256>>>(out, ln2g, ln2b);
}

// round 14
// speedup vs baseline: 1.0924x; 1.0482x over previous
#include <cuda_runtime.h>
#include <cuda_fp16.h>
#include <math.h>
#include <cstdint>

static constexpr int E_  = 8;
static constexpr int B_  = 8;
static constexpr int S_  = 512;
static constexpr int D_  = 768;
static constexpr int H_  = 12;
static constexpr int DH_ = 64;
static constexpr int DFF_= 3072;
static constexpr float SCALE_ = 0.03608439182435161f;  // 768^-0.5
static constexpr float QSC_   = 0.05205923094702504f;  // SCALE_ * log2(e)

// ---------------- scratch (device globals; allocation-free rule) ----------------
__device__ __align__(16) __half g_Qh [E_*B_*H_*S_*DH_];
__device__ __align__(16) __half g_Kh [E_*B_*H_*S_*DH_];
__device__ __align__(16) __half g_Vh [E_*B_*H_*S_*DH_];
__device__ __align__(16) __half g_ctx_h[(size_t)E_*B_*S_*D_];
__device__ __align__(16) float  g_cmp [E_*B_*8*D_];
__device__ __align__(16) float  g_feat[E_*B_*D_];
__device__ int    g_sel [B_];
__device__ __align__(16) float  g_att_sel[B_*S_*D_];
__device__ __align__(16) float  g_h   [B_*S_*D_];
__device__ __align__(16) __half g_h_h [B_*S_*D_];
__device__ __align__(16) __half g_mid_h[B_*S_*DFF_];
__device__ __align__(16) float  g_pre2[B_*S_*D_];
// fp16 converted operands
__device__ __align__(16) __half g_Xh   [B_*S_*D_];
__device__ __align__(16) __half g_Wqkvh[E_*H_*3*DH_*D_];
__device__ __align__(16) __half g_Wdh  [E_*D_*D_];
__device__ __align__(16) __half g_W1h  [E_*DFF_*D_];
__device__ __align__(16) __half g_W2h  [E_*D_*DFF_];

// ---------------- PTX helpers ----------------
__device__ __forceinline__ void cpasync16(uint32_t dst, const void* src) {
    asm volatile("cp.async.cg.shared.global [%0], [%1], 16;"
                 :: "r"(dst), "l"(src) : "memory");
}
#define CP_COMMIT() asm volatile("cp.async.commit_group;" ::: "memory")
#define CP_WAIT0()  asm volatile("cp.async.wait_group 0;"  ::: "memory")
#define CP_WAIT1()  asm volatile("cp.async.wait_group 1;"  ::: "memory")

__device__ __forceinline__ void ldm_x4(uint32_t& r0, uint32_t& r1,
                                       uint32_t& r2, uint32_t& r3, uint32_t addr) {
    asm volatile("ldmatrix.sync.aligned.m8n8.x4.shared.b16 {%0,%1,%2,%3}, [%4];"
                 : "=r"(r0), "=r"(r1), "=r"(r2), "=r"(r3) : "r"(addr));
}
__device__ __forceinline__ void ldm_x4_t(uint32_t& r0, uint32_t& r1,
                                         uint32_t& r2, uint32_t& r3, uint32_t addr) {
    asm volatile("ldmatrix.sync.aligned.m8n8.x4.trans.shared.b16 {%0,%1,%2,%3}, [%4];"
                 : "=r"(r0), "=r"(r1), "=r"(r2), "=r"(r3) : "r"(addr));
}
__device__ __forceinline__ void mma16816(float* c, const uint32_t* a, const uint32_t* b) {
    asm volatile(
        "mma.sync.aligned.m16n8k16.row.col.f32.f16.f16.f32 "
        "{%0,%1,%2,%3},{%4,%5,%6,%7},{%8,%9},{%0,%1,%2,%3};"
        : "+f"(c[0]), "+f"(c[1]), "+f"(c[2]), "+f"(c[3])
        : "r"(a[0]), "r"(a[1]), "r"(a[2]), "r"(a[3]), "r"(b[0]), "r"(b[1]));
}
__device__ __forceinline__ uint32_t f22u(float a, float b) {
    __half2 h = __floats2half2_rn(a, b);
    return *(uint32_t*)&h;
}
__device__ __forceinline__ uint32_t h2exp2(uint32_t a) {
    uint32_t d;
    asm("ex2.approx.f16x2 %0, %1;" : "=r"(d) : "r"(a));
    return d;
}

// ---------------- block reduction ----------------
__device__ __forceinline__ float blockSum256(float v) {
    __shared__ float sh[8];
    int lane = threadIdx.x & 31, w = threadIdx.x >> 5;
    #pragma unroll
    for (int o = 16; o; o >>= 1) v += __shfl_xor_sync(0xffffffffu, v, o);
    if (lane == 0) sh[w] = v;
    __syncthreads();
    if (w == 0) {
        float t = (lane < 8) ? sh[lane] : 0.f;
        #pragma unroll
        for (int o = 4; o; o >>= 1) t += __shfl_xor_sync(0xffffffffu, t, o);
        if (lane == 0) sh[0] = t;
    }
    __syncthreads();
    float r = sh[0];
    __syncthreads();
    return r;
}

// ---------------- fp32 -> fp16 converters ----------------
template<int T>
__global__ void cvt_k(const float* __restrict__ src, int n) {
    __half* dst = (T == 0) ? g_Xh : g_Wqkvh;
    int i = (blockIdx.x * 256 + threadIdx.x) * 4;
    if (i >= n) return;
    float4 v = *(const float4*)&src[i];
    *(__half2*)&dst[i]     = __floats2half2_rn(v.x, v.y);
    *(__half2*)&dst[i + 2] = __floats2half2_rn(v.z, v.w);
}

// selection-gated converters (run after routing; skip unselected experts)
template<int T>
__global__ void cvt_sel_k(const float* __restrict__ src) {
    constexpr int PER = (T == 2) ? D_*D_ : DFF_*D_;
    __half* dst = (T == 2) ? g_Wdh : (T == 3) ? g_W1h : g_W2h;
    int i = (blockIdx.x * 256 + threadIdx.x) * 4;
    int e = i / PER;
    bool need = false;
    #pragma unroll
    for (int b = 0; b < B_; b++) need |= (g_sel[b] == e);
    if (!need) return;
    float4 v = *(const float4*)&src[i];
    *(__half2*)&dst[i]     = __floats2half2_rn(v.x, v.y);
    *(__half2*)&dst[i + 2] = __floats2half2_rn(v.z, v.w);
}

// ---------------- HMMA GEMM 128x128, 2-stage (proven R11 config) -----------------
// MODE 0: QKV   z=e, A=Xh,           W=Wqkvh[e] -> scatter g_Q/K/V (fp16, Q pre-scaled)
// MODE 1: dense z=b, A=ctx_h[sel,b], W=Wdh[sel]+bd -> g_att_sel (fp32)
// MODE 2: ffn1  z=b, A=g_h_h[b],     W=W1h[sel]+b1, gelu -> g_mid_h
// MODE 3: ffn2  z=b, A=g_mid_h[b],   W=W2h[sel]+b2, +g_h -> g_pre2
static constexpr int TPAD  = 40;
static constexpr int TILEB = 128 * TPAD * 2;
static constexpr int BUFB  = 2 * TILEB;

template<int MODE>
__global__ void __launch_bounds__(256) hgemm_k(const float* __restrict__ bias,
                                               int K, int NIT)
{
    __shared__ __align__(128) __half smbuf[2 * 2 * 128 * TPAD];
    const uint32_t smb = (uint32_t)__cvta_generic_to_shared(smbuf);

    const int tid = threadIdx.x, lane = tid & 31, wid = tid >> 5;
    const int wm = (wid & 1) * 64, wn = (wid >> 1) * 32;
    const int z = blockIdx.z;
    const int bm = blockIdx.x * 128, bn = blockIdx.y * 128;

    const __half* A; const __half* W; const float* bvec = nullptr;
    if (MODE == 0) {
        A = g_Xh; W = g_Wqkvh + (size_t)z * (H_*3*DH_) * D_;
    } else if (MODE == 1) {
        int e = g_sel[z];
        A = g_ctx_h + ((size_t)(e * B_ + z)) * S_ * D_;
        W = g_Wdh + (size_t)e * D_ * D_;   bvec = bias + e * D_;
    } else if (MODE == 2) {
        int e = g_sel[z];
        A = g_h_h + (size_t)z * S_ * D_;
        W = g_W1h + (size_t)e * DFF_ * D_; bvec = bias + e * DFF_;
    } else {
        int e = g_sel[z];
        A = g_mid_h + (size_t)z * S_ * DFF_;
        W = g_W2h + (size_t)e * D_ * DFF_; bvec = bias + e * D_;
    }

    auto load_tile = [&](int buf, int k0) {
        #pragma unroll
        for (int j = 0; j < 4; j++) {
            int i = tid + 256 * j;
            int row = (i & 511) >> 2, chunk = i & 3;
            const __half* src = (i < 512)
                ? &A[(size_t)(bm + row) * K + k0 + chunk * 8]
                : &W[(size_t)(bn + row) * K + k0 + chunk * 8];
            uint32_t dst = smb + buf * BUFB + ((i < 512) ? 0 : TILEB)
                         + (row * TPAD + chunk * 8) * 2;
            cpasync16(dst, src);
        }
        CP_COMMIT();
    };

    float acc[4][4][4];
    #pragma unroll
    for (int mi = 0; mi < 4; mi++)
        #pragma unroll
        for (int nj = 0; nj < 4; nj++)
            #pragma unroll
            for (int q = 0; q < 4; q++) acc[mi][nj][q] = 0.f;

    load_tile(0, 0);

    for (int it = 0; it < NIT; ++it) {
        CP_WAIT0();
        __syncthreads();
        if (it + 1 < NIT) load_tile((it + 1) & 1, (it + 1) * 32);

        const uint32_t base = smb + (it & 1) * BUFB;
        #pragma unroll
        for (int kst = 0; kst < 2; kst++) {
            uint32_t a[4][4];
            #pragma unroll
            for (int mi = 0; mi < 4; mi++) {
                int row = wm + mi * 16 + (lane & 15);
                uint32_t ad = base + (row * TPAD + kst * 16 + (lane >> 4) * 8) * 2;
                ldm_x4(a[mi][0], a[mi][1], a[mi][2], a[mi][3], ad);
            }
            uint32_t b[4][2];
            #pragma unroll
            for (int nh = 0; nh < 2; nh++) {
                int nrow = wn + nh * 16 + (lane & 7) + ((lane >> 4) & 1) * 8;
                int koff = ((lane >> 3) & 1) * 8;
                uint32_t bd = base + TILEB + (nrow * TPAD + kst * 16 + koff) * 2;
                ldm_x4(b[nh*2][0], b[nh*2][1], b[nh*2+1][0], b[nh*2+1][1], bd);
            }
            #pragma unroll
            for (int mi = 0; mi < 4; mi++)
                #pragma unroll
                for (int nj = 0; nj < 4; nj++)
                    mma16816(acc[mi][nj], a[mi], b[nj]);
        }
        __syncthreads();
    }

    #pragma unroll
    for (int mi = 0; mi < 4; mi++) {
        #pragma unroll
        for (int nj = 0; nj < 4; nj++) {
            int r0 = bm + wm + mi * 16 + (lane >> 2);
            int c0 = bn + wn + nj * 8 + (lane & 3) * 2;
            #pragma unroll
            for (int half_ = 0; half_ < 2; half_++) {
                int m = r0 + half_ * 8;
                float v0 = acc[mi][nj][half_ * 2 + 0];
                float v1 = acc[mi][nj][half_ * 2 + 1];
                int n = c0;
                if (MODE == 0) {
                    int hh = n / 192, rr = n % 192, w4 = rr >> 6, d = rr & 63;
                    int b8 = m >> 9, s = m & 511;
                    size_t idx = ((((size_t)z * B_ + b8) * H_ + hh) * S_ + s) * DH_ + d;
                    if (w4 == 0)
                        *(__half2*)&g_Qh[idx] = __floats2half2_rn(v0 * QSC_, v1 * QSC_);
                    else if (w4 == 1)
                        *(__half2*)&g_Kh[idx] = __floats2half2_rn(v0, v1);
                    else
                        *(__half2*)&g_Vh[idx] = __floats2half2_rn(v0, v1);
                } else if (MODE == 1) {
                    *(float2*)&g_att_sel[((size_t)z * S_ + m) * D_ + n] =
                        make_float2(v0 + bvec[n], v1 + bvec[n + 1]);
                } else if (MODE == 2) {
                    float x0 = v0 + bvec[n], x1 = v1 + bvec[n + 1];
                    x0 = 0.5f * x0 * (1.f + erff(x0 * 0.70710678118654752f));
                    x1 = 0.5f * x1 * (1.f + erff(x1 * 0.70710678118654752f));
                    *(__half2*)&g_mid_h[((size_t)z * S_ + m) * DFF_ + n] =
                        __floats2half2_rn(x0, x1);
                } else {
                    size_t o = ((size_t)z * S_ + m) * D_ + n;
                    float2 hr = *(const float2*)&g_h[o];
                    *(float2*)&g_pre2[o] =
                        make_float2(v0 + bvec[n] + hr.x, v1 + bvec[n + 1] + hr.y);
                }
            }
        }
    }
}

// ---------------- HMMA flash attention (exp2 domain, fp16 P, sum-via-MMA) --------
static constexpr int FA_SMEM = 55808;

__global__ void __launch_bounds__(256, 2) fattn_k(const int* __restrict__ mask)
{
    extern __shared__ __align__(128) char smem[];
    const uint32_t smb = (uint32_t)__cvta_generic_to_shared(smem);
    const uint32_t smQ = smb;
    const uint32_t smK = smb + 18432;
    const uint32_t smV = smb + 36864;
    float* mk = (float*)(smem + 55296);

    const int tid = threadIdx.x, lane = tid & 31, w = tid >> 5;
    const int i0 = blockIdx.x * 128, h = blockIdx.y, eb = blockIdx.z;
    const int b = eb & 7;
    const size_t hb = ((size_t)eb * H_ + h) * S_ * DH_;
    const __half* Qg = g_Qh + hb;
    const __half* Kg = g_Kh + hb;
    const __half* Vg = g_Vh + hb;

    #pragma unroll
    for (int j = 0; j < 4; j++) {
        int q = tid + 256 * j;
        int r = q >> 3, c = q & 7;
        cpasync16(smQ + r * 144 + c * 16, Qg + (size_t)(i0 + r) * 64 + c * 8);
    }
    #pragma unroll
    for (int j = 0; j < 4; j++) {
        int q = tid + 256 * j;
        int jr = (q & 511) >> 3, c = q & 7;
        const __half* src = (q < 512) ? (Kg + (size_t)jr * 64 + c * 8)
                                      : (Vg + (size_t)jr * 64 + c * 8);
        cpasync16(((q < 512) ? smK : smV) + jr * 144 + c * 16, src);
    }
    CP_COMMIT();
    if (tid < 64) mk[tid] = mask[b * S_ + tid] ? 0.f : -1e30f;

    float o[8][4];
    #pragma unroll
    for (int nd = 0; nd < 8; nd++)
        #pragma unroll
        for (int q = 0; q < 4; q++) o[nd][q] = 0.f;
    float m_run[2] = {-3.0e38f, -3.0e38f}, l_run[2] = {0.f, 0.f};
    uint32_t qa[4][4];

    const int kr = (lane & 7) + ((lane >> 4) & 1) * 8;
    const int kc = ((lane >> 3) & 1) * 8;
    const int vr = (lane & 7) + ((lane >> 3) & 1) * 8;
    const int vc = ((lane >> 4) & 1) * 8;
    const int cbase = 2 * (lane & 3);
    const uint32_t ONEB[2] = {0x3C003C00u, 0x3C003C00u};

    for (int jt = 0; jt < 8; jt++) {
        const int buf = jt & 1;
        if (jt < 7) {
            const int nb = buf ^ 1;
            const int j0n = (jt + 1) * 64;
            #pragma unroll
            for (int j = 0; j < 4; j++) {
                int q = tid + 256 * j;
                int jr = (q & 511) >> 3, c = q & 7;
                const __half* src = (q < 512) ? (Kg + (size_t)(j0n + jr) * 64 + c * 8)
                                              : (Vg + (size_t)(j0n + jr) * 64 + c * 8);
                cpasync16(((q < 512) ? smK : smV) + nb * 9216 + jr * 144 + c * 16, src);
            }
            CP_COMMIT();
            if (tid < 64) mk[nb * 64 + tid] = mask[b * S_ + j0n + tid] ? 0.f : -1e30f;
            CP_WAIT1();
        } else {
            CP_WAIT0();
        }
        __syncthreads();

        if (jt == 0) {
            #pragma unroll
            for (int kst = 0; kst < 4; kst++) {
                uint32_t ad = smQ + (w * 16 + (lane & 15)) * 144
                            + (kst * 16 + (lane >> 4) * 8) * 2;
                ldm_x4(qa[kst][0], qa[kst][1], qa[kst][2], qa[kst][3], ad);
            }
        }

        // S = Q K^T (log2 domain via pre-scaled Q)
        float sc[8][4];
        #pragma unroll
        for (int jb = 0; jb < 8; jb++)
            #pragma unroll
            for (int q = 0; q < 4; q++) sc[jb][q] = 0.f;
        const uint32_t kbase = smK + buf * 9216;
        #pragma unroll
        for (int kst = 0; kst < 4; kst++) {
            #pragma unroll
            for (int jb2 = 0; jb2 < 4; jb2++) {
                uint32_t addr = kbase + (jb2 * 16 + kr) * 144 + (kst * 16 + kc) * 2;
                uint32_t r4[4];
                ldm_x4(r4[0], r4[1], r4[2], r4[3], addr);
                mma16816(sc[2*jb2],     qa[kst], &r4[0]);
                mma16816(sc[2*jb2 + 1], qa[kst], &r4[2]);
            }
        }

        // mask + running max
        const float* mkb = mk + buf * 64;
        float mxA = -3.0e38f, mxB = -3.0e38f;
        #pragma unroll
        for (int jb = 0; jb < 8; jb++) {
            float m0 = mkb[jb * 8 + cbase], m1 = mkb[jb * 8 + cbase + 1];
            sc[jb][0] += m0;
            sc[jb][1] += m1;
            sc[jb][2] += m0;
            sc[jb][3] += m1;
            mxA = fmaxf(mxA, fmaxf(sc[jb][0], sc[jb][1]));
            mxB = fmaxf(mxB, fmaxf(sc[jb][2], sc[jb][3]));
        }
        mxA = fmaxf(mxA, __shfl_xor_sync(0xffffffffu, mxA, 1));
        mxA = fmaxf(mxA, __shfl_xor_sync(0xffffffffu, mxA, 2));
        mxB = fmaxf(mxB, __shfl_xor_sync(0xffffffffu, mxB, 1));
        mxB = fmaxf(mxB, __shfl_xor_sync(0xffffffffu, mxB, 2));
        float mA = fmaxf(m_run[0], mxA), mB = fmaxf(m_run[1], mxB);
        float cA = exp2f(m_run[0] - mA), cB = exp2f(m_run[1] - mB);
        m_run[0] = mA; m_run[1] = mB;

        // P in fp16 directly: ex2.approx.f16x2 of (sc - m)
        uint32_t pA[8], pB[8];
        #pragma unroll
        for (int jb = 0; jb < 8; jb++) {
            pA[jb] = h2exp2(f22u(sc[jb][0] - mA, sc[jb][1] - mA));
            pB[jb] = h2exp2(f22u(sc[jb][2] - mB, sc[jb][3] - mB));
        }

        #pragma unroll
        for (int nd = 0; nd < 8; nd++) {
            o[nd][0] *= cA; o[nd][1] *= cA;
            o[nd][2] *= cB; o[nd][3] *= cB;
        }

        // O += P V ; row sums via ones-MMA (fp32 accum over the same fp16 P)
        float osum[4] = {0.f, 0.f, 0.f, 0.f};
        const uint32_t vbase = smV + buf * 9216;
        #pragma unroll
        for (int kst = 0; kst < 4; kst++) {
            uint32_t pa[4];
            pa[0] = pA[2*kst];     pa[1] = pB[2*kst];
            pa[2] = pA[2*kst + 1]; pa[3] = pB[2*kst + 1];
            mma16816(osum, pa, ONEB);
            #pragma unroll
            for (int nd2 = 0; nd2 < 4; nd2++) {
                uint32_t addr = vbase + (kst * 16 + vr) * 144 + (nd2 * 16 + vc) * 2;
                uint32_t r4[4];
                ldm_x4_t(r4[0], r4[1], r4[2], r4[3], addr);
                mma16816(o[2*nd2],     pa, &r4[0]);
                mma16816(o[2*nd2 + 1], pa, &r4[2]);
            }
        }
        l_run[0] = l_run[0] * cA + osum[0];
        l_run[1] = l_run[1] * cB + osum[2];
        __syncthreads();
    }

    float iA = 1.f / l_run[0], iB = 1.f / l_run[1];
    int rA = i0 + w * 16 + (lane >> 2);
    int rB = rA + 8;
    #pragma unroll
    for (int nd = 0; nd < 8; nd++) {
        int d0 = h * 64 + nd * 8 + cbase;
        *(__half2*)&g_ctx_h[((size_t)eb * S_ + rA) * D_ + d0] =
            __floats2half2_rn(o[nd][0] * iA, o[nd][1] * iA);
        *(__half2*)&g_ctx_h[((size_t)eb * S_ + rB) * D_ + d0] =
            __floats2half2_rn(o[nd][2] * iB, o[nd][3] * iB);
    }
}

// ---------------- partial seq-mean of ctx ----------------------------------------
__global__ void cmean_k()
{
    int eb = blockIdx.x, ch = blockIdx.y, t = threadIdx.x;
    const __half* base = g_ctx_h + ((size_t)eb * S_ + ch * 64) * D_;
    for (int c2 = t; c2 < 384; c2 += 256) {
        float sx = 0.f, sy = 0.f;
        for (int i = 0; i < 64; i++) {
            float2 f = __half22float2(*(const __half2*)&base[(size_t)i * D_ + 2*c2]);
            sx += f.x; sy += f.y;
        }
        *(float2*)&g_cmp[((size_t)eb * 8 + ch) * D_ + 2*c2] = make_float2(sx, sy);
    }
}

// ---------------- routing micro-GEMM: feat = mean(ctx)@Wd^T + bd -----------------
__global__ void featgemm_k(const float* __restrict__ Wd, const float* __restrict__ bd)
{
    __shared__ float cm[D_];
    int eb = blockIdx.x, t = threadIdx.x, e = eb >> 3;
    for (int c = t; c < D_; c += 256) {
        float s = 0.f;
        #pragma unroll
        for (int ch = 0; ch < 8; ch++) s += g_cmp[((size_t)eb * 8 + ch) * D_ + c];
        cm[c] = s * (1.f / 512.f);
    }
    __syncthreads();
    const float* We = Wd + (size_t)e * D_ * D_;
    for (int n = t; n < D_; n += 256) {
        float s = bd[e * D_ + n];
        const float4* wr = (const float4*)&We[(size_t)n * D_];
        for (int d4 = 0; d4 < D_/4; d4++) {
            float4 w = wr[d4];
            s += cm[d4*4]*w.x + cm[d4*4+1]*w.y + cm[d4*4+2]*w.z + cm[d4*4+3]*w.w;
        }
        g_feat[(size_t)eb * D_ + n] = s;
    }
}

// ---------------- route: sel[b] = argmin_e ||feat[e,b]-centers[e]|| ---------------
__global__ void route_k(const float* __restrict__ centers)
{
    int b = blockIdx.x, t = threadIdx.x;
    float bv = 3.4e38f; int bi = 0;
    for (int e = 0; e < E_; e++) {
        float ps = 0.f;
        for (int c = t; c < D_; c += 256) {
            float d0 = g_feat[(e*B_ + b)*D_ + c] - centers[e*D_ + c];
            ps += d0 * d0;
        }
        float tot = blockSum256(ps);
        if (t == 0 && tot < bv) { bv = tot; bi = e; }
    }
    if (t == 0) g_sel[b] = bi;
}

// ---------------- LN1: h = LN(att_sel + x) ----------------
__global__ void ln1_k(const float* __restrict__ X,
                      const float* __restrict__ gma, const float* __restrict__ bta)
{
    int s = blockIdx.x, b = blockIdx.y, t = threadIdx.x;
    int e = g_sel[b];
    const float* ar = g_att_sel + ((size_t)b*S_ + s) * D_;
    const float* xr = X + ((size_t)b*S_ + s) * D_;
    float v[3], sm = 0.f;
    #pragma unroll
    for (int i = 0; i < 3; i++) { int c = t + i*256; v[i] = ar[c] + xr[c]; sm += v[i]; }
    float mean = blockSum256(sm) * (1.f / D_);
    float q = 0.f;
    #pragma unroll
    for (int i = 0; i < 3; i++) { float d0 = v[i] - mean; q += d0 * d0; }
    float inv = rsqrtf(blockSum256(q) * (1.f / D_) + 1e-12f);
    float*  hr  = g_h   + ((size_t)b*S_ + s) * D_;
    __half* hrh = g_h_h + ((size_t)b*S_ + s) * D_;
    #pragma unroll
    for (int i = 0; i < 3; i++) {
        int c = t + i*256;
        float val = (v[i] - mean) * inv * gma[e*D_ + c] + bta[e*D_ + c];
        hr[c]  = val;
        hrh[c] = __float2half_rn(val);
    }
}

// ---------------- LN2: out = LN(pre2) ----------------
__global__ void ln2_k(float* __restrict__ out,
                      const float* __restrict__ gma, const float* __restrict__ bta)
{
    int s = blockIdx.x, b = blockIdx.y, t = threadIdx.x;
    int e = g_sel[b];
    const float* pr = g_pre2 + ((size_t)b*S_ + s) * D_;
    float v[3], sm = 0.f;
    #pragma unroll
    for (int i = 0; i < 3; i++) { int c = t + i*256; v[i] = pr[c]; sm += v[i]; }
    float mean = blockSum256(sm) * (1.f / D_);
    float q = 0.f;
    #pragma unroll
    for (int i = 0; i < 3; i++) { float d0 = v[i] - mean; q += d0 * d0; }
    float inv = rsqrtf(blockSum256(q) * (1.f / D_) + 1e-12f);
    float* orow = out + ((size_t)b*S_ + s) * D_;
    #pragma unroll
    for (int i = 0; i < 3; i++) {
        int c = t + i*256;
        orow[c] = (v[i] - mean) * inv * gma[e*D_ + c] + bta[e*D_ + c];
    }
}

// ---------------- launch ----------------
extern "C" void kernel_launch(void* const* d_in, const int* in_sizes, int n_in,
                              void* d_out, int out_size)
{
    const float* X      = (const float*)d_in[0];
    const int*   mask   = (const int*)  d_in[1];
    const float* Wqkv   = (const float*)d_in[2];
    const float* Wd     = (const float*)d_in[3];
    const float* bd     = (const float*)d_in[4];
    const float* ln1g   = (const float*)d_in[5];
    const float* ln1b   = (const float*)d_in[6];
    const float* W1     = (const float*)d_in[7];
    const float* b1     = (const float*)d_in[8];
    const float* W2     = (const float*)d_in[9];
    const float* b2     = (const float*)d_in[10];
    const float* ln2g   = (const float*)d_in[11];
    const float* ln2b   = (const float*)d_in[12];
    const float* centers= (const float*)d_in[13];
    float* out = (float*)d_out;

    cudaFuncSetAttribute(fattn_k, cudaFuncAttributeMaxDynamicSharedMemorySize, FA_SMEM);

    const int nX    = B_*S_*D_;
    const int nWqkv = E_*H_*3*DH_*D_;
    const int nWd   = E_*D_*D_;
    const int nW1   = E_*DFF_*D_;
    const int nW2   = E_*D_*DFF_;

    // 0) convert X and Wqkv (rest gated on routing)
    cvt_k<0><<<nX/1024,    256>>>(X,    nX);
    cvt_k<1><<<nWqkv/1024, 256>>>(Wqkv, nWqkv);

    // 1) QKV for all experts: M=4096, N=2304, K=768, z=e
    hgemm_k<0><<<dim3(32, 18, 8), 256>>>(nullptr, D_, 24);
    // 2) HMMA flash attention (all e,b) -> ctx fp16
    fattn_k<<<dim3(4, 12, 64), 256, FA_SMEM>>>(mask);
    // 3) routing: mean(ctx) -> micro dense (fp32 Wd) -> argmin
    cmean_k<<<dim3(64, 8), 256>>>();
    featgemm_k<<<64, 256>>>(Wd, bd);
    route_k<<<B_, 256>>>(centers);
    // 3b) convert only selected experts' weights
    cvt_sel_k<2><<<nWd/1024, 256>>>(Wd);
    cvt_sel_k<3><<<nW1/1024, 256>>>(W1);
    cvt_sel_k<4><<<nW2/1024, 256>>>(W2);
    // 4) dense projection ONLY for selected expert: M=512, N=768, K=768, z=b
    hgemm_k<1><<<dim3(4, 6, 8), 256>>>(bd, D_, 24);
    // 5) LN1
    ln1_k<<<dim3(S_, B_), 256>>>(X, ln1g, ln1b);
    // 6) FFN1 + GELU: M=512, N=3072, K=768, z=b
    hgemm_k<2><<<dim3(4, 24, 8), 256>>>(b1, D_, 24);
    // 7) FFN2 + bias + residual: M=512, N=768, K=3072, z=b
    hgemm_k<3><<<dim3(4, 6, 8), 256>>>(b2, DFF_, 96);
    // 8) LN2 -> output
    ln2_k<<<dim3(S_, B_), 256>>>(out, ln2g, ln2b);
}

// round 15
// speedup vs baseline: 1.1814x; 1.0815x over previous
#include <cuda_runtime.h>
#include <cuda_fp16.h>
#include <math.h>
#include <cstdint>

static constexpr int E_  = 8;
static constexpr int B_  = 8;
static constexpr int S_  = 512;
static constexpr int D_  = 768;
static constexpr int H_  = 12;
static constexpr int DH_ = 64;
static constexpr int DFF_= 3072;
static constexpr float QSC_   = 0.05205923094702504f;  // 768^-0.5 * log2(e)

// ---------------- scratch (device globals; allocation-free rule) ----------------
__device__ __align__(16) __half g_Qh [E_*B_*H_*S_*DH_];
__device__ __align__(16) __half g_Kh [E_*B_*H_*S_*DH_];
__device__ __align__(16) __half g_Vh [E_*B_*H_*S_*DH_];
__device__ __align__(16) __half g_ctx_h[(size_t)E_*B_*S_*D_];
__device__ __align__(16) float  g_cmp [E_*B_*8*D_];
__device__ __align__(16) float  g_feat[E_*B_*D_];
__device__ int    g_sel [B_];
__device__ __align__(16) float  g_att_sel[B_*S_*D_];
__device__ __align__(16) float  g_h   [B_*S_*D_];
__device__ __align__(16) __half g_h_h [B_*S_*D_];
__device__ __align__(16) __half g_mid_h[B_*S_*DFF_];
__device__ __align__(16) float  g_pre2[B_*S_*D_];
// fp16 converted operands
__device__ __align__(16) __half g_Xh   [B_*S_*D_];
__device__ __align__(16) __half g_Wqkvh[E_*H_*3*DH_*D_];
__device__ __align__(16) __half g_Wdh  [E_*D_*D_];
__device__ __align__(16) __half g_W1h  [E_*DFF_*D_];
__device__ __align__(16) __half g_W2h  [E_*D_*DFF_];

// ---------------- PTX helpers ----------------
__device__ __forceinline__ void cpasync16(uint32_t dst, const void* src) {
    asm volatile("cp.async.cg.shared.global [%0], [%1], 16;"
                 :: "r"(dst), "l"(src) : "memory");
}
#define CP_COMMIT() asm volatile("cp.async.commit_group;" ::: "memory")
#define CP_WAIT0()  asm volatile("cp.async.wait_group 0;"  ::: "memory")
#define CP_WAIT1()  asm volatile("cp.async.wait_group 1;"  ::: "memory")

__device__ __forceinline__ void ldm_x4(uint32_t& r0, uint32_t& r1,
                                       uint32_t& r2, uint32_t& r3, uint32_t addr) {
    asm volatile("ldmatrix.sync.aligned.m8n8.x4.shared.b16 {%0,%1,%2,%3}, [%4];"
                 : "=r"(r0), "=r"(r1), "=r"(r2), "=r"(r3) : "r"(addr));
}
__device__ __forceinline__ void ldm_x4_t(uint32_t& r0, uint32_t& r1,
                                         uint32_t& r2, uint32_t& r3, uint32_t addr) {
    asm volatile("ldmatrix.sync.aligned.m8n8.x4.trans.shared.b16 {%0,%1,%2,%3}, [%4];"
                 : "=r"(r0), "=r"(r1), "=r"(r2), "=r"(r3) : "r"(addr));
}
__device__ __forceinline__ void mma16816(float* c, const uint32_t* a, const uint32_t* b) {
    asm volatile(
        "mma.sync.aligned.m16n8k16.row.col.f32.f16.f16.f32 "
        "{%0,%1,%2,%3},{%4,%5,%6,%7},{%8,%9},{%0,%1,%2,%3};"
        : "+f"(c[0]), "+f"(c[1]), "+f"(c[2]), "+f"(c[3])
        : "r"(a[0]), "r"(a[1]), "r"(a[2]), "r"(a[3]), "r"(b[0]), "r"(b[1]));
}
__device__ __forceinline__ uint32_t f22u(float a, float b) {
    __half2 h = __floats2half2_rn(a, b);
    return *(uint32_t*)&h;
}
__device__ __forceinline__ uint32_t h2exp2(uint32_t a) {
    uint32_t d;
    asm("ex2.approx.f16x2 %0, %1;" : "=r"(d) : "r"(a));
    return d;
}

// ---------------- block reduction ----------------
__device__ __forceinline__ float blockSum256(float v) {
    __shared__ float sh[8];
    int lane = threadIdx.x & 31, w = threadIdx.x >> 5;
    #pragma unroll
    for (int o = 16; o; o >>= 1) v += __shfl_xor_sync(0xffffffffu, v, o);
    if (lane == 0) sh[w] = v;
    __syncthreads();
    if (w == 0) {
        float t = (lane < 8) ? sh[lane] : 0.f;
        #pragma unroll
        for (int o = 4; o; o >>= 1) t += __shfl_xor_sync(0xffffffffu, t, o);
        if (lane == 0) sh[0] = t;
    }
    __syncthreads();
    float r = sh[0];
    __syncthreads();
    return r;
}

// ---------------- fp32 -> fp16 converters ----------------
template<int T>
__global__ void cvt_k(const float* __restrict__ src, int n) {
    __half* dst = (T == 0) ? g_Xh : g_Wqkvh;
    int i = (blockIdx.x * 256 + threadIdx.x) * 4;
    if (i >= n) return;
    float4 v = *(const float4*)&src[i];
    *(__half2*)&dst[i]     = __floats2half2_rn(v.x, v.y);
    *(__half2*)&dst[i + 2] = __floats2half2_rn(v.z, v.w);
}

template<int T>
__global__ void cvt_sel_k(const float* __restrict__ src) {
    constexpr int PER = (T == 2) ? D_*D_ : DFF_*D_;
    __half* dst = (T == 2) ? g_Wdh : (T == 3) ? g_W1h : g_W2h;
    int i = (blockIdx.x * 256 + threadIdx.x) * 4;
    int e = i / PER;
    bool need = false;
    #pragma unroll
    for (int b = 0; b < B_; b++) need |= (g_sel[b] == e);
    if (!need) return;
    float4 v = *(const float4*)&src[i];
    *(__half2*)&dst[i]     = __floats2half2_rn(v.x, v.y);
    *(__half2*)&dst[i + 2] = __floats2half2_rn(v.z, v.w);
}

// ---------------- QKV GEMM: 128x128, BK=64, 2-stage, dynamic smem ----------------
static constexpr int QTP   = 72;                  // padded halves per row (BK=64)
static constexpr int QTILE = 128 * QTP * 2;       // 18432 B per operand
static constexpr int QSTG  = 2 * QTILE;           // 36864 B per stage
static constexpr int QSM   = 2 * QSTG;            // 73728 B dynamic

__global__ void __launch_bounds__(256) hgemmq_k()
{
    extern __shared__ __align__(128) char smraw[];
    const uint32_t smb = (uint32_t)__cvta_generic_to_shared(smraw);

    const int tid = threadIdx.x, lane = tid & 31, wid = tid >> 5;
    const int wm = (wid & 1) * 64, wn = (wid >> 1) * 32;
    const int z = blockIdx.z;
    const int bm = blockIdx.x * 128, bn = blockIdx.y * 128;

    const __half* A = g_Xh;
    const __half* W = g_Wqkvh + (size_t)z * (H_*3*DH_) * D_;

    auto load_tile = [&](int buf, int k0) {
        #pragma unroll
        for (int j = 0; j < 8; j++) {
            int i = tid + 256 * j;
            int row = (i & 1023) >> 3, chunk = i & 7;
            const __half* src = (i < 1024)
                ? &A[(size_t)(bm + row) * D_ + k0 + chunk * 8]
                : &W[(size_t)(bn + row) * D_ + k0 + chunk * 8];
            uint32_t dst = smb + buf * QSTG + ((i < 1024) ? 0 : QTILE)
                         + (row * QTP + chunk * 8) * 2;
            cpasync16(dst, src);
        }
        CP_COMMIT();
    };

    float acc[4][4][4];
    #pragma unroll
    for (int mi = 0; mi < 4; mi++)
        #pragma unroll
        for (int nj = 0; nj < 4; nj++)
            #pragma unroll
            for (int q = 0; q < 4; q++) acc[mi][nj][q] = 0.f;

    load_tile(0, 0);

    for (int it = 0; it < 12; ++it) {
        CP_WAIT0();
        __syncthreads();
        if (it + 1 < 12) load_tile((it + 1) & 1, (it + 1) * 64);

        const uint32_t base = smb + (it & 1) * QSTG;
        #pragma unroll
        for (int kst = 0; kst < 4; kst++) {
            uint32_t a[4][4];
            #pragma unroll
            for (int mi = 0; mi < 4; mi++) {
                int row = wm + mi * 16 + (lane & 15);
                uint32_t ad = base + (row * QTP + kst * 16 + (lane >> 4) * 8) * 2;
                ldm_x4(a[mi][0], a[mi][1], a[mi][2], a[mi][3], ad);
            }
            uint32_t b[4][2];
            #pragma unroll
            for (int nh = 0; nh < 2; nh++) {
                int nrow = wn + nh * 16 + (lane & 7) + ((lane >> 4) & 1) * 8;
                int koff = ((lane >> 3) & 1) * 8;
                uint32_t bd = base + QTILE + (nrow * QTP + kst * 16 + koff) * 2;
                ldm_x4(b[nh*2][0], b[nh*2][1], b[nh*2+1][0], b[nh*2+1][1], bd);
            }
            #pragma unroll
            for (int mi = 0; mi < 4; mi++)
                #pragma unroll
                for (int nj = 0; nj < 4; nj++)
                    mma16816(acc[mi][nj], a[mi], b[nj]);
        }
        __syncthreads();
    }

    #pragma unroll
    for (int mi = 0; mi < 4; mi++) {
        #pragma unroll
        for (int nj = 0; nj < 4; nj++) {
            int r0 = bm + wm + mi * 16 + (lane >> 2);
            int c0 = bn + wn + nj * 8 + (lane & 3) * 2;
            #pragma unroll
            for (int half_ = 0; half_ < 2; half_++) {
                int m = r0 + half_ * 8;
                float v0 = acc[mi][nj][half_ * 2 + 0];
                float v1 = acc[mi][nj][half_ * 2 + 1];
                int n = c0;
                int hh = n / 192, rr = n % 192, w4 = rr >> 6, d = rr & 63;
                int b8 = m >> 9, s = m & 511;
                size_t idx = ((((size_t)z * B_ + b8) * H_ + hh) * S_ + s) * DH_ + d;
                if (w4 == 0)
                    *(__half2*)&g_Qh[idx] = __floats2half2_rn(v0 * QSC_, v1 * QSC_);
                else if (w4 == 1)
                    *(__half2*)&g_Kh[idx] = __floats2half2_rn(v0, v1);
                else
                    *(__half2*)&g_Vh[idx] = __floats2half2_rn(v0, v1);
            }
        }
    }
}

// ---------------- HMMA GEMM 128x128, BK=32, 2-stage (FFN1) -----------------------
static constexpr int TPAD  = 40;
static constexpr int TILEB = 128 * TPAD * 2;
static constexpr int BUFB  = 2 * TILEB;

__global__ void __launch_bounds__(256) hgemm_k(const float* __restrict__ bias,
                                               int K, int NIT)
{
    __shared__ __align__(128) __half smbuf[2 * 2 * 128 * TPAD];
    const uint32_t smb = (uint32_t)__cvta_generic_to_shared(smbuf);

    const int tid = threadIdx.x, lane = tid & 31, wid = tid >> 5;
    const int wm = (wid & 1) * 64, wn = (wid >> 1) * 32;
    const int z = blockIdx.z;
    const int bm = blockIdx.x * 128, bn = blockIdx.y * 128;

    int e = g_sel[z];
    const __half* A = g_h_h + (size_t)z * S_ * D_;
    const __half* W = g_W1h + (size_t)e * DFF_ * D_;
    const float* bvec = bias + e * DFF_;

    auto load_tile = [&](int buf, int k0) {
        #pragma unroll
        for (int j = 0; j < 4; j++) {
            int i = tid + 256 * j;
            int row = (i & 511) >> 2, chunk = i & 3;
            const __half* src = (i < 512)
                ? &A[(size_t)(bm + row) * K + k0 + chunk * 8]
                : &W[(size_t)(bn + row) * K + k0 + chunk * 8];
            uint32_t dst = smb + buf * BUFB + ((i < 512) ? 0 : TILEB)
                         + (row * TPAD + chunk * 8) * 2;
            cpasync16(dst, src);
        }
        CP_COMMIT();
    };

    float acc[4][4][4];
    #pragma unroll
    for (int mi = 0; mi < 4; mi++)
        #pragma unroll
        for (int nj = 0; nj < 4; nj++)
            #pragma unroll
            for (int q = 0; q < 4; q++) acc[mi][nj][q] = 0.f;

    load_tile(0, 0);

    for (int it = 0; it < NIT; ++it) {
        CP_WAIT0();
        __syncthreads();
        if (it + 1 < NIT) load_tile((it + 1) & 1, (it + 1) * 32);

        const uint32_t base = smb + (it & 1) * BUFB;
        #pragma unroll
        for (int kst = 0; kst < 2; kst++) {
            uint32_t a[4][4];
            #pragma unroll
            for (int mi = 0; mi < 4; mi++) {
                int row = wm + mi * 16 + (lane & 15);
                uint32_t ad = base + (row * TPAD + kst * 16 + (lane >> 4) * 8) * 2;
                ldm_x4(a[mi][0], a[mi][1], a[mi][2], a[mi][3], ad);
            }
            uint32_t b[4][2];
            #pragma unroll
            for (int nh = 0; nh < 2; nh++) {
                int nrow = wn + nh * 16 + (lane & 7) + ((lane >> 4) & 1) * 8;
                int koff = ((lane >> 3) & 1) * 8;
                uint32_t bd = base + TILEB + (nrow * TPAD + kst * 16 + koff) * 2;
                ldm_x4(b[nh*2][0], b[nh*2][1], b[nh*2+1][0], b[nh*2+1][1], bd);
            }
            #pragma unroll
            for (int mi = 0; mi < 4; mi++)
                #pragma unroll
                for (int nj = 0; nj < 4; nj++)
                    mma16816(acc[mi][nj], a[mi], b[nj]);
        }
        __syncthreads();
    }

    #pragma unroll
    for (int mi = 0; mi < 4; mi++) {
        #pragma unroll
        for (int nj = 0; nj < 4; nj++) {
            int r0 = bm + wm + mi * 16 + (lane >> 2);
            int c0 = bn + wn + nj * 8 + (lane & 3) * 2;
            #pragma unroll
            for (int half_ = 0; half_ < 2; half_++) {
                int m = r0 + half_ * 8;
                float v0 = acc[mi][nj][half_ * 2 + 0];
                float v1 = acc[mi][nj][half_ * 2 + 1];
                int n = c0;
                float x0 = v0 + bvec[n], x1 = v1 + bvec[n + 1];
                x0 = 0.5f * x0 * (1.f + erff(x0 * 0.70710678118654752f));
                x1 = 0.5f * x1 * (1.f + erff(x1 * 0.70710678118654752f));
                *(__half2*)&g_mid_h[((size_t)z * S_ + m) * DFF_ + n] =
                    __floats2half2_rn(x0, x1);
            }
        }
    }
}

// ---------------- HMMA GEMM 64x128, BK=32 (dense / ffn2; better grid fill) -------
static constexpr int ATILE64 = 64 * TPAD * 2;    // 5120 B
static constexpr int STG64   = ATILE64 + TILEB;  // 15360 B per stage

template<int MODE>  // 1 = dense, 3 = ffn2
__global__ void __launch_bounds__(256) hgemm64_k(const float* __restrict__ bias,
                                                 int K, int NIT)
{
    __shared__ __align__(128) __half smbuf[2 * STG64 / 2];
    const uint32_t smb = (uint32_t)__cvta_generic_to_shared(smbuf);

    const int tid = threadIdx.x, lane = tid & 31, wid = tid >> 5;
    const int wm = (wid & 1) * 32, wn = (wid >> 1) * 32;
    const int z = blockIdx.z;
    const int bm = blockIdx.x * 64, bn = blockIdx.y * 128;

    int e = g_sel[z];
    const __half* A; const __half* W; const float* bvec;
    if (MODE == 1) {
        A = g_ctx_h + ((size_t)(e * B_ + z)) * S_ * D_;
        W = g_Wdh + (size_t)e * D_ * D_;   bvec = bias + e * D_;
    } else {
        A = g_mid_h + (size_t)z * S_ * DFF_;
        W = g_W2h + (size_t)e * D_ * DFF_; bvec = bias + e * D_;
    }

    auto load_tile = [&](int buf, int k0) {
        #pragma unroll
        for (int j = 0; j < 3; j++) {
            int i = tid + 256 * j;
            uint32_t dst; const __half* src;
            if (i < 256) {
                int row = i >> 2, chunk = i & 3;
                src = &A[(size_t)(bm + row) * K + k0 + chunk * 8];
                dst = smb + buf * STG64 + (row * TPAD + chunk * 8) * 2;
            } else {
                int i2 = i - 256;
                int row = i2 >> 2, chunk = i2 & 3;
                src = &W[(size_t)(bn + row) * K + k0 + chunk * 8];
                dst = smb + buf * STG64 + ATILE64 + (row * TPAD + chunk * 8) * 2;
            }
            cpasync16(dst, src);
        }
        CP_COMMIT();
    };

    float acc[2][4][4];
    #pragma unroll
    for (int mi = 0; mi < 2; mi++)
        #pragma unroll
        for (int nj = 0; nj < 4; nj++)
            #pragma unroll
            for (int q = 0; q < 4; q++) acc[mi][nj][q] = 0.f;

    load_tile(0, 0);

    for (int it = 0; it < NIT; ++it) {
        CP_WAIT0();
        __syncthreads();
        if (it + 1 < NIT) load_tile((it + 1) & 1, (it + 1) * 32);

        const uint32_t base = smb + (it & 1) * STG64;
        #pragma unroll
        for (int kst = 0; kst < 2; kst++) {
            uint32_t a[2][4];
            #pragma unroll
            for (int mi = 0; mi < 2; mi++) {
                int row = wm + mi * 16 + (lane & 15);
                uint32_t ad = base + (row * TPAD + kst * 16 + (lane >> 4) * 8) * 2;
                ldm_x4(a[mi][0], a[mi][1], a[mi][2], a[mi][3], ad);
            }
            uint32_t b[4][2];
            #pragma unroll
            for (int nh = 0; nh < 2; nh++) {
                int nrow = wn + nh * 16 + (lane & 7) + ((lane >> 4) & 1) * 8;
                int koff = ((lane >> 3) & 1) * 8;
                uint32_t bd = base + ATILE64 + (nrow * TPAD + kst * 16 + koff) * 2;
                ldm_x4(b[nh*2][0], b[nh*2][1], b[nh*2+1][0], b[nh*2+1][1], bd);
            }
            #pragma unroll
            for (int mi = 0; mi < 2; mi++)
                #pragma unroll
                for (int nj = 0; nj < 4; nj++)
                    mma16816(acc[mi][nj], a[mi], b[nj]);
        }
        __syncthreads();
    }

    #pragma unroll
    for (int mi = 0; mi < 2; mi++) {
        #pragma unroll
        for (int nj = 0; nj < 4; nj++) {
            int r0 = bm + wm + mi * 16 + (lane >> 2);
            int c0 = bn + wn + nj * 8 + (lane & 3) * 2;
            #pragma unroll
            for (int half_ = 0; half_ < 2; half_++) {
                int m = r0 + half_ * 8;
                float v0 = acc[mi][nj][half_ * 2 + 0];
                float v1 = acc[mi][nj][half_ * 2 + 1];
                int n = c0;
                if (MODE == 1) {
                    *(float2*)&g_att_sel[((size_t)z * S_ + m) * D_ + n] =
                        make_float2(v0 + bvec[n], v1 + bvec[n + 1]);
                } else {
                    size_t o = ((size_t)z * S_ + m) * D_ + n;
                    float2 hr = *(const float2*)&g_h[o];
                    *(float2*)&g_pre2[o] =
                        make_float2(v0 + bvec[n] + hr.x, v1 + bvec[n + 1] + hr.y);
                }
            }
        }
    }
}

// ---------------- HMMA flash attention (exp2 domain, fp16 P, sum-via-MMA) --------
static constexpr int FA_SMEM = 55808;

__global__ void __launch_bounds__(256, 2) fattn_k(const int* __restrict__ mask)
{
    extern __shared__ __align__(128) char smem[];
    const uint32_t smb = (uint32_t)__cvta_generic_to_shared(smem);
    const uint32_t smQ = smb;
    const uint32_t smK = smb + 18432;
    const uint32_t smV = smb + 36864;
    float* mk = (float*)(smem + 55296);

    const int tid = threadIdx.x, lane = tid & 31, w = tid >> 5;
    const int i0 = blockIdx.x * 128, h = blockIdx.y, eb = blockIdx.z;
    const int b = eb & 7;
    const size_t hb = ((size_t)eb * H_ + h) * S_ * DH_;
    const __half* Qg = g_Qh + hb;
    const __half* Kg = g_Kh + hb;
    const __half* Vg = g_Vh + hb;

    #pragma unroll
    for (int j = 0; j < 4; j++) {
        int q = tid + 256 * j;
        int r = q >> 3, c = q & 7;
        cpasync16(smQ + r * 144 + c * 16, Qg + (size_t)(i0 + r) * 64 + c * 8);
    }
    #pragma unroll
    for (int j = 0; j < 4; j++) {
        int q = tid + 256 * j;
        int jr = (q & 511) >> 3, c = q & 7;
        const __half* src = (q < 512) ? (Kg + (size_t)jr * 64 + c * 8)
                                      : (Vg + (size_t)jr * 64 + c * 8);
        cpasync16(((q < 512) ? smK : smV) + jr * 144 + c * 16, src);
    }
    CP_COMMIT();
    if (tid < 64) mk[tid] = mask[b * S_ + tid] ? 0.f : -1e30f;

    float o[8][4];
    #pragma unroll
    for (int nd = 0; nd < 8; nd++)
        #pragma unroll
        for (int q = 0; q < 4; q++) o[nd][q] = 0.f;
    float m_run[2] = {-3.0e38f, -3.0e38f}, l_run[2] = {0.f, 0.f};
    uint32_t qa[4][4];

    const int kr = (lane & 7) + ((lane >> 4) & 1) * 8;
    const int kc = ((lane >> 3) & 1) * 8;
    const int vr = (lane & 7) + ((lane >> 3) & 1) * 8;
    const int vc = ((lane >> 4) & 1) * 8;
    const int cbase = 2 * (lane & 3);
    const uint32_t ONEB[2] = {0x3C003C00u, 0x3C003C00u};

    for (int jt = 0; jt < 8; jt++) {
        const int buf = jt & 1;
        if (jt < 7) {
            const int nb = buf ^ 1;
            const int j0n = (jt + 1) * 64;
            #pragma unroll
            for (int j = 0; j < 4; j++) {
                int q = tid + 256 * j;
                int jr = (q & 511) >> 3, c = q & 7;
                const __half* src = (q < 512) ? (Kg + (size_t)(j0n + jr) * 64 + c * 8)
                                              : (Vg + (size_t)(j0n + jr) * 64 + c * 8);
                cpasync16(((q < 512) ? smK : smV) + nb * 9216 + jr * 144 + c * 16, src);
            }
            CP_COMMIT();
            if (tid < 64) mk[nb * 64 + tid] = mask[b * S_ + j0n + tid] ? 0.f : -1e30f;
            CP_WAIT1();
        } else {
            CP_WAIT0();
        }
        __syncthreads();

        if (jt == 0) {
            #pragma unroll
            for (int kst = 0; kst < 4; kst++) {
                uint32_t ad = smQ + (w * 16 + (lane & 15)) * 144
                            + (kst * 16 + (lane >> 4) * 8) * 2;
                ldm_x4(qa[kst][0], qa[kst][1], qa[kst][2], qa[kst][3], ad);
            }
        }

        float sc[8][4];
        #pragma unroll
        for (int jb = 0; jb < 8; jb++)
            #pragma unroll
            for (int q = 0; q < 4; q++) sc[jb][q] = 0.f;
        const uint32_t kbase = smK + buf * 9216;
        #pragma unroll
        for (int kst = 0; kst < 4; kst++) {
            #pragma unroll
            for (int jb2 = 0; jb2 < 4; jb2++) {
                uint32_t addr = kbase + (jb2 * 16 + kr) * 144 + (kst * 16 + kc) * 2;
                uint32_t r4[4];
                ldm_x4(r4[0], r4[1], r4[2], r4[3], addr);
                mma16816(sc[2*jb2],     qa[kst], &r4[0]);
                mma16816(sc[2*jb2 + 1], qa[kst], &r4[2]);
            }
        }

        const float* mkb = mk + buf * 64;
        float mxA = -3.0e38f, mxB = -3.0e38f;
        #pragma unroll
        for (int jb = 0; jb < 8; jb++) {
            float m0 = mkb[jb * 8 + cbase], m1 = mkb[jb * 8 + cbase + 1];
            sc[jb][0] += m0;
            sc[jb][1] += m1;
            sc[jb][2] += m0;
            sc[jb][3] += m1;
            mxA = fmaxf(mxA, fmaxf(sc[jb][0], sc[jb][1]));
            mxB = fmaxf(mxB, fmaxf(sc[jb][2], sc[jb][3]));
        }
        mxA = fmaxf(mxA, __shfl_xor_sync(0xffffffffu, mxA, 1));
        mxA = fmaxf(mxA, __shfl_xor_sync(0xffffffffu, mxA, 2));
        mxB = fmaxf(mxB, __shfl_xor_sync(0xffffffffu, mxB, 1));
        mxB = fmaxf(mxB, __shfl_xor_sync(0xffffffffu, mxB, 2));
        float mA = fmaxf(m_run[0], mxA), mB = fmaxf(m_run[1], mxB);
        float cA = exp2f(m_run[0] - mA), cB = exp2f(m_run[1] - mB);
        m_run[0] = mA; m_run[1] = mB;

        uint32_t pA[8], pB[8];
        #pragma unroll
        for (int jb = 0; jb < 8; jb++) {
            pA[jb] = h2exp2(f22u(sc[jb][0] - mA, sc[jb][1] - mA));
            pB[jb] = h2exp2(f22u(sc[jb][2] - mB, sc[jb][3] - mB));
        }

        #pragma unroll
        for (int nd = 0; nd < 8; nd++) {
            o[nd][0] *= cA; o[nd][1] *= cA;
            o[nd][2] *= cB; o[nd][3] *= cB;
        }

        float osum[4] = {0.f, 0.f, 0.f, 0.f};
        const uint32_t vbase = smV + buf * 9216;
        #pragma unroll
        for (int kst = 0; kst < 4; kst++) {
            uint32_t pa[4];
            pa[0] = pA[2*kst];     pa[1] = pB[2*kst];
            pa[2] = pA[2*kst + 1]; pa[3] = pB[2*kst + 1];
            mma16816(osum, pa, ONEB);
            #pragma unroll
            for (int nd2 = 0; nd2 < 4; nd2++) {
                uint32_t addr = vbase + (kst * 16 + vr) * 144 + (nd2 * 16 + vc) * 2;
                uint32_t r4[4];
                ldm_x4_t(r4[0], r4[1], r4[2], r4[3], addr);
                mma16816(o[2*nd2],     pa, &r4[0]);
                mma16816(o[2*nd2 + 1], pa, &r4[2]);
            }
        }
        l_run[0] = l_run[0] * cA + osum[0];
        l_run[1] = l_run[1] * cB + osum[2];
        __syncthreads();
    }

    float iA = 1.f / l_run[0], iB = 1.f / l_run[1];
    int rA = i0 + w * 16 + (lane >> 2);
    int rB = rA + 8;
    #pragma unroll
    for (int nd = 0; nd < 8; nd++) {
        int d0 = h * 64 + nd * 8 + cbase;
        *(__half2*)&g_ctx_h[((size_t)eb * S_ + rA) * D_ + d0] =
            __floats2half2_rn(o[nd][0] * iA, o[nd][1] * iA);
        *(__half2*)&g_ctx_h[((size_t)eb * S_ + rB) * D_ + d0] =
            __floats2half2_rn(o[nd][2] * iB, o[nd][3] * iB);
    }
}

// ---------------- partial seq-mean of ctx ----------------------------------------
__global__ void cmean_k()
{
    int eb = blockIdx.x, ch = blockIdx.y, t = threadIdx.x;
    const __half* base = g_ctx_h + ((size_t)eb * S_ + ch * 64) * D_;
    for (int c2 = t; c2 < 384; c2 += 256) {
        float sx = 0.f, sy = 0.f;
        for (int i = 0; i < 64; i++) {
            float2 f = __half22float2(*(const __half2*)&base[(size_t)i * D_ + 2*c2]);
            sx += f.x; sy += f.y;
        }
        *(float2*)&g_cmp[((size_t)eb * 8 + ch) * D_ + 2*c2] = make_float2(sx, sy);
    }
}

// ---------------- routing micro-GEMM: feat = mean(ctx)@Wd^T + bd -----------------
__global__ void featgemm_k(const float* __restrict__ Wd, const float* __restrict__ bd)
{
    __shared__ float cm[D_];
    int eb = blockIdx.x, t = threadIdx.x, e = eb >> 3;
    for (int c = t; c < D_; c += 256) {
        float s = 0.f;
        #pragma unroll
        for (int ch = 0; ch < 8; ch++) s += g_cmp[((size_t)eb * 8 + ch) * D_ + c];
        cm[c] = s * (1.f / 512.f);
    }
    __syncthreads();
    const float* We = Wd + (size_t)e * D_ * D_;
    for (int n = t; n < D_; n += 256) {
        float s = bd[e * D_ + n];
        const float4* wr = (const float4*)&We[(size_t)n * D_];
        for (int d4 = 0; d4 < D_/4; d4++) {
            float4 w = wr[d4];
            s += cm[d4*4]*w.x + cm[d4*4+1]*w.y + cm[d4*4+2]*w.z + cm[d4*4+3]*w.w;
        }
        g_feat[(size_t)eb * D_ + n] = s;
    }
}

// ---------------- route: sel[b] = argmin_e ||feat[e,b]-centers[e]|| ---------------
__global__ void route_k(const float* __restrict__ centers)
{
    int b = blockIdx.x, t = threadIdx.x;
    float bv = 3.4e38f; int bi = 0;
    for (int e = 0; e < E_; e++) {
        float ps = 0.f;
        for (int c = t; c < D_; c += 256) {
            float d0 = g_feat[(e*B_ + b)*D_ + c] - centers[e*D_ + c];
            ps += d0 * d0;
        }
        float tot = blockSum256(ps);
        if (t == 0 && tot < bv) { bv = tot; bi = e; }
    }
    if (t == 0) g_sel[b] = bi;
}

// ---------------- LN1: h = LN(att_sel + x) ----------------
__global__ void ln1_k(const float* __restrict__ X,
                      const float* __restrict__ gma, const float* __restrict__ bta)
{
    int s = blockIdx.x, b = blockIdx.y, t = threadIdx.x;
    int e = g_sel[b];
    const float* ar = g_att_sel + ((size_t)b*S_ + s) * D_;
    const float* xr = X + ((size_t)b*S_ + s) * D_;
    float v[3], sm = 0.f;
    #pragma unroll
    for (int i = 0; i < 3; i++) { int c = t + i*256; v[i] = ar[c] + xr[c]; sm += v[i]; }
    float mean = blockSum256(sm) * (1.f / D_);
    float q = 0.f;
    #pragma unroll
    for (int i = 0; i < 3; i++) { float d0 = v[i] - mean; q += d0 * d0; }
    float inv = rsqrtf(blockSum256(q) * (1.f / D_) + 1e-12f);
    float*  hr  = g_h   + ((size_t)b*S_ + s) * D_;
    __half* hrh = g_h_h + ((size_t)b*S_ + s) * D_;
    #pragma unroll
    for (int i = 0; i < 3; i++) {
        int c = t + i*256;
        float val = (v[i] - mean) * inv * gma[e*D_ + c] + bta[e*D_ + c];
        hr[c]  = val;
        hrh[c] = __float2half_rn(val);
    }
}

// ---------------- LN2: out = LN(pre2) ----------------
__global__ void ln2_k(float* __restrict__ out,
                      const float* __restrict__ gma, const float* __restrict__ bta)
{
    int s = blockIdx.x, b = blockIdx.y, t = threadIdx.x;
    int e = g_sel[b];
    const float* pr = g_pre2 + ((size_t)b*S_ + s) * D_;
    float v[3], sm = 0.f;
    #pragma unroll
    for (int i = 0; i < 3; i++) { int c = t + i*256; v[i] = pr[c]; sm += v[i]; }
    float mean = blockSum256(sm) * (1.f / D_);
    float q = 0.f;
    #pragma unroll
    for (int i = 0; i < 3; i++) { float d0 = v[i] - mean; q += d0 * d0; }
    float inv = rsqrtf(blockSum256(q) * (1.f / D_) + 1e-12f);
    float* orow = out + ((size_t)b*S_ + s) * D_;
    #pragma unroll
    for (int i = 0; i < 3; i++) {
        int c = t + i*256;
        orow[c] = (v[i] - mean) * inv * gma[e*D_ + c] + bta[e*D_ + c];
    }
}

// ---------------- launch ----------------
extern "C" void kernel_launch(void* const* d_in, const int* in_sizes, int n_in,
                              void* d_out, int out_size)
{
    const float* X      = (const float*)d_in[0];
    const int*   mask   = (const int*)  d_in[1];
    const float* Wqkv   = (const float*)d_in[2];
    const float* Wd     = (const float*)d_in[3];
    const float* bd     = (const float*)d_in[4];
    const float* ln1g   = (const float*)d_in[5];
    const float* ln1b   = (const float*)d_in[6];
    const float* W1     = (const float*)d_in[7];
    const float* b1     = (const float*)d_in[8];
    const float* W2     = (const float*)d_in[9];
    const float* b2     = (const float*)d_in[10];
    const float* ln2g   = (const float*)d_in[11];
    const float* ln2b   = (const float*)d_in[12];
    const float* centers= (const float*)d_in[13];
    float* out = (float*)d_out;

    cudaFuncSetAttribute(fattn_k, cudaFuncAttributeMaxDynamicSharedMemorySize, FA_SMEM);
    cudaFuncSetAttribute(hgemmq_k, cudaFuncAttributeMaxDynamicSharedMemorySize, QSM);

    const int nX    = B_*S_*D_;
    const int nWqkv = E_*H_*3*DH_*D_;
    const int nWd   = E_*D_*D_;
    const int nW1   = E_*DFF_*D_;
    const int nW2   = E_*D_*DFF_;

    // 0) convert X and Wqkv (rest gated on routing)
    cvt_k<0><<<nX/1024,    256>>>(X,    nX);
    cvt_k<1><<<nWqkv/1024, 256>>>(Wqkv, nWqkv);

    // 1) QKV for all experts: M=4096, N=2304, K=768, z=e (BK=64)
    hgemmq_k<<<dim3(32, 18, 8), 256, QSM>>>();
    // 2) HMMA flash attention (all e,b) -> ctx fp16
    fattn_k<<<dim3(4, 12, 64), 256, FA_SMEM>>>(mask);
    // 3) routing: mean(ctx) -> micro dense (fp32 Wd) -> argmin
    cmean_k<<<dim3(64, 8), 256>>>();
    featgemm_k<<<64, 256>>>(Wd, bd);
    route_k<<<B_, 256>>>(centers);
    // 3b) convert only selected experts' weights
    cvt_sel_k<2><<<nWd/1024, 256>>>(Wd);
    cvt_sel_k<3><<<nW1/1024, 256>>>(W1);
    cvt_sel_k<4><<<nW2/1024, 256>>>(W2);
    // 4) dense projection (selected expert only): M=512, N=768, K=768, 64-row tiles
    hgemm64_k<1><<<dim3(8, 6, 8), 256>>>(bd, D_, 24);
    // 5) LN1
    ln1_k<<<dim3(S_, B_), 256>>>(X, ln1g, ln1b);
    // 6) FFN1 + GELU: M=512, N=3072, K=768, z=b
    hgemm_k<<<dim3(4, 24, 8), 256>>>(b1, D_, 24);
    // 7) FFN2 + bias + residual: M=512, N=768, K=3072, 64-row tiles
    hgemm64_k<3><<<dim3(8, 6, 8), 256>>>(b2, DFF_, 96);
    // 8) LN2 -> output
    ln2_k<<<dim3(S_, B_), 256>>>(out, ln2g, ln2b);
}